// round 13
// baseline (speedup 1.0000x reference)
#include <cuda_runtime.h>
#include <math.h>

typedef unsigned long long u64;

// ================= constants =================
__constant__ float c_elev[32] = {
    -30.67f,-29.33f,-28.0f,-26.66f,-25.33f,-24.0f,-22.67f,-21.33f,
    -20.0f,-18.67f,-17.33f,-16.0f,-14.67f,-13.33f,-12.0f,-10.67f,
    -9.33f,-8.0f,-6.66f,-5.33f,-4.0f,-2.67f,-1.33f,0.0f,
    1.33f,2.67f,4.0f,5.33f,6.67f,8.0f,9.33f,10.67f};

// ================= scratch (no allocations allowed) =================
// GEMM weights duplicated: [k][2*OT], pair (2o,2o+1) holds the same value.
__device__ __align__(16) float g_wcombT[128*256];
__device__ __align__(16) float g_bcomb[128];
__device__ __align__(16) float g_woaT[128*288];
__device__ __align__(16) float g_boa[144+4];
__device__ __align__(16) float g_wyT[256*256];
__device__ __align__(16) float g_by[128];
__device__ __align__(16) float g_pqT[128*256];
__device__ __align__(16) float g_rh1T[144*256];
__device__ __align__(16) float g_qs1T[144*256];
__device__ __align__(16) float g_rh2T[1152*64];      // conv weights NOT duplicated
__device__ __align__(16) float g_v[(size_t)4*65536*128];
__device__ __align__(16) float g_Q0[(size_t)4*16384*128];
__device__ __align__(16) float g_t1[(size_t)4*128*16384];
__device__ __align__(16) float g_t2[(size_t)4*64*16384];
__device__ __align__(16) float g_stats[128];
__device__ __align__(16) float g_ref[4*16384*2];
__device__ __align__(16) float g_sig[4*16384*2];
__device__ __align__(16) float g_qt[(size_t)4*16384*128];
__device__ __align__(16) float g_offaw[(size_t)4*16384*144];
__device__ __align__(16) float g_attn[(size_t)4*16384*128];

// ================= f32x2 helpers =================
__device__ __forceinline__ u64 ffma2(u64 a, u64 b, u64 c){
    u64 d;
    asm("fma.rn.f32x2 %0, %1, %2, %3;" : "=l"(d) : "l"(a), "l"(b), "l"(c));
    return d;
}
__device__ __forceinline__ u64 add2(u64 a, u64 b){
    u64 d;
    asm("add.rn.f32x2 %0, %1, %2;" : "=l"(d) : "l"(a), "l"(b));
    return d;
}
__device__ __forceinline__ u64 splat2(float x){
    u64 d; unsigned int xi = __float_as_uint(x);
    asm("mov.b64 %0, {%1, %1};" : "=l"(d) : "r"(xi));
    return d;
}
__device__ __forceinline__ void unpack2(u64 v, float& lo, float& hi){
    unsigned int a, b;
    asm("mov.b64 {%0, %1}, %2;" : "=r"(a), "=r"(b) : "l"(v));
    lo = __uint_as_float(a); hi = __uint_as_float(b);
}

// ================= scalar helpers =================
__device__ __forceinline__ float gelu_f(float x){
    return 0.5f * x * (1.0f + erff(x * 0.7071067811865476f));
}
__device__ __forceinline__ float sigm_f(float x){
    return 1.0f / (1.0f + expf(-x));
}
__device__ __forceinline__ void geom_f(int h, int w, float& ux, float& uy, float& uz){
    float az = ((float)w - 256.0f) * (3.14159265358979323846f / 256.0f);
    float el = c_elev[31 - h] * 0.017453292519943295f;
    float sa, ca, se, ce;
    sincosf(az, &sa, &ca);
    sincosf(el, &se, &ce);
    ux = ca * ce; uy = sa * ce; uz = se;
}

// ================= weight folding + duplicated transposes =================
__global__ void __launch_bounds__(256) k_prep(
    const float* __restrict__ vp_w, const float* __restrict__ pv_w,
    const float* __restrict__ pv_b, const float* __restrict__ vp_b,
    const float* __restrict__ so_w, const float* __restrict__ so_b,
    const float* __restrict__ aw_w, const float* __restrict__ aw_b,
    const float* __restrict__ qs2_w, const float* __restrict__ qs2_b,
    const float* __restrict__ po_w, const float* __restrict__ po_b,
    const float* __restrict__ op_w, const float* __restrict__ op_b,
    const float* __restrict__ pq_w, const float* __restrict__ rh1_w,
    const float* __restrict__ qs1_w, const float* __restrict__ rh2_w,
    float* __restrict__ wcombT, float* __restrict__ bcomb,
    float* __restrict__ woaT, float* __restrict__ boa,
    float* __restrict__ wyT, float* __restrict__ by,
    float* __restrict__ pqT, float* __restrict__ rh1T,
    float* __restrict__ qs1T, float* __restrict__ rh2T)
{
    int t = blockIdx.x * 256 + threadIdx.x;
    if (t < 16384){
        int d = t >> 7, c = t & 127;
        float s = 0.f;
        #pragma unroll 8
        for (int o = 0; o < 128; ++o) s = fmaf(vp_w[d*128+o], pv_w[o*128+c], s);
        wcombT[c*256 + 2*d] = s; wcombT[c*256 + 2*d + 1] = s;
    } else if (t < 16512){
        int d = t - 16384;
        float s = vp_b[d];
        for (int o = 0; o < 128; ++o) s = fmaf(vp_w[d*128+o], pv_b[o], s);
        bcomb[d] = s;
    } else if (t < 34944){
        int i = t - 16512;
        int r = i >> 7, c = i & 127;
        const float* rw = (r < 96) ? (so_w + r*128) : (aw_w + (r-96)*128);
        float s = 0.f;
        #pragma unroll 8
        for (int o = 0; o < 128; ++o) s = fmaf(rw[o], qs2_w[o*128+c], s);
        woaT[c*288 + 2*r] = s; woaT[c*288 + 2*r + 1] = s;
    } else if (t < 35088){
        int r = t - 34944;
        const float* rw = (r < 96) ? (so_w + r*128) : (aw_w + (r-96)*128);
        float s = (r < 96) ? so_b[r] : aw_b[r-96];
        for (int o = 0; o < 128; ++o) s = fmaf(rw[o], qs2_b[o], s);
        boa[r] = s;
    } else if (t < 67856){
        int i = t - 35088;
        int d = i >> 8, c = i & 255;
        const float* cw = (c < 128) ? (qs2_w + c) : (op_w + (c - 128));
        float s = 0.f;
        #pragma unroll 8
        for (int o = 0; o < 128; ++o) s = fmaf(po_w[d*128+o], cw[o*128], s);
        wyT[c*256 + 2*d] = s; wyT[c*256 + 2*d + 1] = s;
    } else if (t < 67984){
        int d = t - 67856;
        float s = po_b[d];
        for (int o = 0; o < 128; ++o) s = fmaf(po_w[d*128+o], qs2_b[o] + op_b[o], s);
        by[d] = s;
    } else if (t < 84368){
        int i = t - 67984;
        int o = i >> 7, k = i & 127;
        float s = pq_w[o*128 + k];
        pqT[k*256 + 2*o] = s; pqT[k*256 + 2*o + 1] = s;
    } else if (t < 102800){
        int i = t - 84368;
        int k = i >> 7, o = i & 127;
        float s = (k < 131) ? rh1_w[o*131 + k] : 0.f;
        rh1T[k*256 + 2*o] = s; rh1T[k*256 + 2*o + 1] = s;
    } else if (t < 121232){
        int i = t - 102800;
        int k = i >> 7, o = i & 127;
        float s = (k < 130) ? qs1_w[o*130 + k] : 0.f;
        qs1T[k*256 + 2*o] = s; qs1T[k*256 + 2*o + 1] = s;
    } else if (t < 194960){
        int i = t - 121232;
        int r = i >> 6, o = i & 63;
        rh2T[r*64 + o] = rh2_w[o*1152 + r];
    }
}

// ===== conflict-free f32x2 tile GEMM: 128 px x OT, dup-W, pixel-pair accum =====
// WT duplicated k-major [NCH*16][2*OT].
// AMODE: 0 pixel-major A[row][128]; 1 channel-major A[b][k][npix];
//        2 pixel-major + 3 geom ch (KTOT=131); 3 pixel-major + 2 aux ch (KTOT=130);
//        4 K=256: k<128 from A, k>=128 from aux (pixel-major)
// OMODE: 0 out [row][OT]; 1 out [b][o][npix]
// EPI:   0 bias; 1 bias+gelu
template<int KTOT, int OT, int AMODE, int OMODE, int EPI>
__global__ void __launch_bounds__(16*(OT/8), 2) k_gemm4(
    const float* __restrict__ A, const float* __restrict__ WT,
    const float* __restrict__ bias, float* __restrict__ out,
    const float* __restrict__ aux, int npix)
{
    constexpr int NT   = 16*(OT/8);
    constexpr int NCH  = (KTOT + 15) / 16;
    constexpr int AS   = 132;          // As row stride (floats), 16B-aligned rows
    constexpr int ASB  = 16*AS;        // floats per A buffer
    constexpr int WSB  = 16*OT;        // u64 per W buffer
    constexpr int NWLD = (8*OT) / NT;  // float4 W-loads per thread (=4)
    extern __shared__ char smem_raw[];
    float* Asm = (float*)smem_raw;                         // 2 buffers
    u64*   Wsm = (u64*)(smem_raw + 2*ASB*4);               // 2 buffers

    const int b    = blockIdx.y;
    const int pix0 = blockIdx.x * 128;
    const int tid  = threadIdx.x;
    const int pxA  = (tid & 15) * 4;   // group A: px pxA..pxA+3; group B: +64
    const int o0   = (tid >> 4) * 8;

    u64 acc[4][8];   // [px-pair: A0,A1,B0,B1][output]
    #pragma unroll
    for (int i = 0; i < 4; ++i)
        #pragma unroll
        for (int j = 0; j < 8; ++j) acc[i][j] = 0ull;

    float4 aR[2], wR[NWLD];

    auto isTail = [&](int kc){
        return (AMODE == 2 || AMODE == 3) && (kc*16 + 16 > 128);
    };
    auto loadW = [&](int kc){
        const float* src = WT + (size_t)kc*16*2*OT;
        #pragma unroll
        for (int l = 0; l < NWLD; ++l){
            int i = tid + l*NT;
            wR[l] = *reinterpret_cast<const float4*>(src + i*4);
        }
    };
    auto storeW = [&](int buf){
        u64* Wb = Wsm + buf*WSB;
        #pragma unroll
        for (int l = 0; l < NWLD; ++l){
            int i = tid + l*NT;
            int k = i / (OT/2), q = i % (OT/2);
            *(reinterpret_cast<float4*>(Wb + k*OT) + q) = wR[l];
        }
    };
    auto loadA = [&](int kc){
        const int kbase = kc*16;
        if constexpr (AMODE == 1){
            #pragma unroll
            for (int l = 0; l < 2; ++l){
                int i = tid + l*NT;
                if (NT == 256 || i < 512){
                    int k = i >> 5, p4 = (i & 31) * 4;
                    aR[l] = *reinterpret_cast<const float4*>(
                        A + ((size_t)(b*KTOT + kbase + k))*(size_t)npix + pix0 + p4);
                }
            }
        } else {
            const float* src = A; int koff = kbase;
            if constexpr (AMODE == 4){ if (kc >= 8){ src = aux; koff = kbase - 128; } }
            #pragma unroll
            for (int l = 0; l < 2; ++l){
                int i = tid + l*NT;
                if (NT == 256 || i < 512){
                    int px = i >> 2, q = i & 3;
                    aR[l] = *reinterpret_cast<const float4*>(
                        src + ((size_t)b*npix + pix0 + px)*128 + koff + q*4);
                }
            }
        }
    };
    auto storeA = [&](int buf){
        float* Ab = Asm + buf*ASB;
        if constexpr (AMODE == 1){
            #pragma unroll
            for (int l = 0; l < 2; ++l){
                int i = tid + l*NT;
                if (NT == 256 || i < 512){
                    int k = i >> 5, p4 = (i & 31) * 4;
                    *reinterpret_cast<float4*>(Ab + k*AS + p4) = aR[l];
                }
            }
        } else {
            #pragma unroll
            for (int l = 0; l < 2; ++l){
                int i = tid + l*NT;
                if (NT == 256 || i < 512){
                    int px = i >> 2, q = i & 3;
                    Ab[(q*4+0)*AS + px] = aR[l].x;
                    Ab[(q*4+1)*AS + px] = aR[l].y;
                    Ab[(q*4+2)*AS + px] = aR[l].z;
                    Ab[(q*4+3)*AS + px] = aR[l].w;
                }
            }
        }
    };
    auto tailFill = [&](int buf){
        float* Ab = Asm + buf*ASB;
        constexpr int ZS = (AMODE == 2) ? 3 : 2;
        const float4 z4 = make_float4(0.f, 0.f, 0.f, 0.f);
        for (int i = tid; i < (16 - ZS)*32; i += NT){
            int k = ZS + (i >> 5), p4 = (i & 31) * 4;
            *reinterpret_cast<float4*>(Ab + k*AS + p4) = z4;
        }
        if (tid < 128){
            if constexpr (AMODE == 2){
                int p = pix0 + tid;
                float ux, uy, uz; geom_f(p >> 9, p & 511, ux, uy, uz);
                Ab[0*AS + tid] = ux;
                Ab[1*AS + tid] = uy;
                Ab[2*AS + tid] = uz;
            }
            if constexpr (AMODE == 3){
                const float2 s = *reinterpret_cast<const float2*>(
                    aux + ((size_t)b*npix + pix0 + tid)*2);
                Ab[0*AS + tid] = s.x;
                Ab[1*AS + tid] = s.y;
            }
        }
    };
    auto compute = [&](int buf){
        const float* Ab = Asm + buf*ASB;
        const u64*   Wb = Wsm + buf*WSB;
        #pragma unroll
        for (int k = 0; k < 16; ++k){
            const ulonglong2 aA = *reinterpret_cast<const ulonglong2*>(Ab + k*AS + pxA);
            const ulonglong2 aB = *reinterpret_cast<const ulonglong2*>(Ab + k*AS + pxA + 64);
            u64 a0 = aA.x, a1 = aA.y, a2 = aB.x, a3 = aB.y;
            const u64* wp = Wb + k*OT + o0;
            const ulonglong2 w01 = *reinterpret_cast<const ulonglong2*>(wp);
            const ulonglong2 w23 = *reinterpret_cast<const ulonglong2*>(wp + 2);
            const ulonglong2 w45 = *reinterpret_cast<const ulonglong2*>(wp + 4);
            const ulonglong2 w67 = *reinterpret_cast<const ulonglong2*>(wp + 6);
            u64 w[8] = {w01.x, w01.y, w23.x, w23.y, w45.x, w45.y, w67.x, w67.y};
            #pragma unroll
            for (int j = 0; j < 8; ++j){
                acc[0][j] = ffma2(a0, w[j], acc[0][j]);
                acc[1][j] = ffma2(a1, w[j], acc[1][j]);
                acc[2][j] = ffma2(a2, w[j], acc[2][j]);
                acc[3][j] = ffma2(a3, w[j], acc[3][j]);
            }
        }
    };

    // prologue
    loadW(0);
    if (!isTail(0)) loadA(0);
    storeW(0);
    if (isTail(0)) tailFill(0); else storeA(0);
    __syncthreads();

    for (int kc = 0; kc < NCH; ++kc){
        const int cur = kc & 1, nxt = cur ^ 1;
        if (kc + 1 < NCH){
            loadW(kc + 1);
            if (!isTail(kc + 1)) loadA(kc + 1);
        }
        compute(cur);
        if (kc + 1 < NCH){
            storeW(nxt);
            if (isTail(kc + 1)) tailFill(nxt); else storeA(nxt);
            __syncthreads();
        }
    }

    // bias splats
    u64 bb[8];
    #pragma unroll
    for (int j = 0; j < 8; ++j) bb[j] = splat2(bias[o0 + j]);

    if constexpr (OMODE == 0){
        #pragma unroll
        for (int g = 0; g < 2; ++g){
            #pragma unroll
            for (int pp = 0; pp < 2; ++pp){
                int ai = g*2 + pp;
                float fe[8], fo[8];
                #pragma unroll
                for (int j = 0; j < 8; ++j){
                    u64 v = add2(acc[ai][j], bb[j]);
                    unpack2(v, fe[j], fo[j]);
                }
                if constexpr (EPI == 1){
                    #pragma unroll
                    for (int j = 0; j < 8; ++j){ fe[j] = gelu_f(fe[j]); fo[j] = gelu_f(fo[j]); }
                }
                size_t re = ((size_t)b*npix + pix0 + pxA + g*64 + pp*2)*(size_t)OT + o0;
                *reinterpret_cast<float4*>(out + re)          = make_float4(fe[0], fe[1], fe[2], fe[3]);
                *reinterpret_cast<float4*>(out + re + 4)      = make_float4(fe[4], fe[5], fe[6], fe[7]);
                *reinterpret_cast<float4*>(out + re + OT)     = make_float4(fo[0], fo[1], fo[2], fo[3]);
                *reinterpret_cast<float4*>(out + re + OT + 4) = make_float4(fo[4], fo[5], fo[6], fo[7]);
            }
        }
    } else {
        #pragma unroll
        for (int j = 0; j < 8; ++j){
            u64 v0 = add2(acc[0][j], bb[j]);
            u64 v1 = add2(acc[1][j], bb[j]);
            u64 v2 = add2(acc[2][j], bb[j]);
            u64 v3 = add2(acc[3][j], bb[j]);
            float* base = out + ((size_t)(b*OT + o0 + j))*(size_t)npix + pix0;
            ulonglong2 pA; pA.x = v0; pA.y = v1;
            ulonglong2 pB; pB.x = v2; pB.y = v3;
            *reinterpret_cast<ulonglong2*>(base + pxA)      = pA;
            *reinterpret_cast<ulonglong2*>(base + pxA + 64) = pB;
        }
    }
}

// ====== 3x3 conv, wrap pad (H=32,W=512), 128->64, f32x2 output pairs ==========
__global__ void __launch_bounds__(256, 2) k_conv3(
    const float* __restrict__ hin,  // [b][128][16384]
    const float* __restrict__ wtT,  // [1152][64] transposed
    float* __restrict__ out)        // [b][64][16384]
{
    __shared__ float In[24*260];
    __shared__ float Wc[72*68];
    const int b  = blockIdx.z;
    const int h  = blockIdx.y;
    const int w0 = blockIdx.x * 256;
    const int tid = threadIdx.x;
    const int pxl = (tid & 31) * 8;
    const int o0  = (tid >> 5) * 8;

    u64 acc[8][4];
    #pragma unroll
    for (int i = 0; i < 8; ++i)
        #pragma unroll
        for (int j = 0; j < 4; ++j) acc[i][j] = 0ull;

    float4 wR[5];
    auto loadW = [&](int icc){
        #pragma unroll
        for (int l = 0; l < 5; ++l){
            int i = tid + l*256;
            if (i < 1152)
                wR[l] = reinterpret_cast<const float4*>(wtT)[icc*1152 + i];
        }
    };

    loadW(0);
    for (int icc = 0; icc < 16; ++icc){
        __syncthreads();
        #pragma unroll
        for (int l = 0; l < 5; ++l){
            int i = tid + l*256;
            if (i < 1152){
                int r = i >> 4, o4 = (i & 15) * 4;
                *reinterpret_cast<float4*>(&Wc[r*68 + o4]) = wR[l];
            }
        }
        for (int i = tid; i < 24*258; i += 256){
            int r = i / 258, x = i - r*258;
            int ic = r / 3, ky = r - ic*3;
            int c  = icc*8 + ic;
            int hh = (h + ky + 31) & 31;
            int ww = (w0 + x - 1) & 511;
            In[r*260 + x] = hin[(((size_t)(b*128 + c)) << 14) + (hh << 9) + ww];
        }
        __syncthreads();
        if (icc + 1 < 16) loadW(icc + 1);
        #pragma unroll
        for (int ic = 0; ic < 8; ++ic){
            #pragma unroll
            for (int ky = 0; ky < 3; ++ky){
                const float* inr = &In[(ic*3 + ky)*260 + pxl];
                float a[12];
                *reinterpret_cast<float4*>(&a[0]) = *reinterpret_cast<const float4*>(inr);
                *reinterpret_cast<float4*>(&a[4]) = *reinterpret_cast<const float4*>(inr + 4);
                *reinterpret_cast<float4*>(&a[8]) = *reinterpret_cast<const float4*>(inr + 8);
                u64 as[10];
                #pragma unroll
                for (int x = 0; x < 10; ++x) as[x] = splat2(a[x]);
                #pragma unroll
                for (int kx = 0; kx < 3; ++kx){
                    const u64* wp = reinterpret_cast<const u64*>(
                        &Wc[(ic*9 + ky*3 + kx)*68 + o0]);
                    const ulonglong2 w01 = *reinterpret_cast<const ulonglong2*>(wp);
                    const ulonglong2 w23 = *reinterpret_cast<const ulonglong2*>(wp + 2);
                    u64 w[4] = {w01.x, w01.y, w23.x, w23.y};
                    #pragma unroll
                    for (int px = 0; px < 8; ++px){
                        acc[px][0] = ffma2(as[px+kx], w[0], acc[px][0]);
                        acc[px][1] = ffma2(as[px+kx], w[1], acc[px][1]);
                        acc[px][2] = ffma2(as[px+kx], w[2], acc[px][2]);
                        acc[px][3] = ffma2(as[px+kx], w[3], acc[px][3]);
                    }
                }
            }
        }
    }
    #pragma unroll
    for (int j = 0; j < 4; ++j){
        float ra[8], rb[8];
        #pragma unroll
        for (int px = 0; px < 8; ++px) unpack2(acc[px][j], ra[px], rb[px]);
        float* d0 = out + ((size_t)(b*64 + o0 + 2*j))*16384 + h*512 + w0 + pxl;
        float* d1 = d0 + 16384;
        *reinterpret_cast<float4*>(d0)     = make_float4(ra[0], ra[1], ra[2], ra[3]);
        *reinterpret_cast<float4*>(d0 + 4) = make_float4(ra[4], ra[5], ra[6], ra[7]);
        *reinterpret_cast<float4*>(d1)     = make_float4(rb[0], rb[1], rb[2], rb[3]);
        *reinterpret_cast<float4*>(d1 + 4) = make_float4(rb[4], rb[5], rb[6], rb[7]);
    }
}

// ================= group-norm statistics =================
__global__ void __launch_bounds__(512) k_gnstats(
    const float* __restrict__ x, float* __restrict__ st, int nper)
{
    __shared__ float sh[1024];
    size_t base = (size_t)blockIdx.x * (size_t)nper;
    float s = 0.f, sq = 0.f;
    const float4* xv = reinterpret_cast<const float4*>(x + base);
    int n4 = nper >> 2;
    for (int i = threadIdx.x; i < n4; i += 512){
        float4 v = xv[i];
        s  += v.x + v.y + v.z + v.w;
        sq += v.x*v.x + v.y*v.y + v.z*v.z + v.w*v.w;
    }
    sh[threadIdx.x] = s; sh[512 + threadIdx.x] = sq;
    __syncthreads();
    for (int off = 256; off > 0; off >>= 1){
        if (threadIdx.x < off){
            sh[threadIdx.x]       += sh[threadIdx.x + off];
            sh[512 + threadIdx.x] += sh[512 + threadIdx.x + off];
        }
        __syncthreads();
    }
    if (threadIdx.x == 0){
        float mean = sh[0] / (float)nper;
        float var  = sh[512] / (float)nper - mean*mean;
        st[blockIdx.x*2]     = mean;
        st[blockIdx.x*2 + 1] = rsqrtf(var + 1e-5f);
    }
}

// ================= gn1 apply + gelu, float4, in place =================
__global__ void __launch_bounds__(256) k_gnapply(
    float* __restrict__ x, const float* __restrict__ st,
    const float* __restrict__ gw, const float* __restrict__ gb)
{
    size_t i4 = (size_t)blockIdx.x*256 + threadIdx.x;
    size_t i  = i4 * 4;
    int c  = (int)((i >> 14) & 127);
    int bg = (int)(i >> 21) * 8 + (c >> 4);
    float m = st[bg*2], rs = st[bg*2 + 1];
    float w = gw[c], bb = gb[c];
    float4 v = reinterpret_cast<float4*>(x)[i4];
    v.x = gelu_f((v.x - m) * rs * w + bb);
    v.y = gelu_f((v.y - m) * rs * w + bb);
    v.z = gelu_f((v.z - m) * rs * w + bb);
    v.w = gelu_f((v.w - m) * rs * w + bb);
    reinterpret_cast<float4*>(x)[i4] = v;
}

// ================= gn2-apply + gelu + rh3 + geometry + refs =================
__global__ void __launch_bounds__(256) k_head(
    const float* __restrict__ t2, const float* __restrict__ st2,
    const float* __restrict__ g2w, const float* __restrict__ g2b,
    const float* __restrict__ rh3w, const float* __restrict__ rh3b,
    const float* __restrict__ l2e,
    float* __restrict__ out_mu, float* __restrict__ out_sigma,
    float* __restrict__ refp, float* __restrict__ sigf)
{
    int idx = blockIdx.x*256 + threadIdx.x;   // 0..65535
    int b = idx >> 14, pix = idx & 16383;
    float o0 = 0.f, o1 = 0.f;
    #pragma unroll 4
    for (int c = 0; c < 64; ++c){
        int bg = b*8 + (c >> 3);
        float m  = st2[bg*2], rs = st2[bg*2 + 1];
        float v  = t2[((size_t)(b*64 + c))*16384 + pix];
        float hg = gelu_f((v - m) * rs * g2w[c] + g2b[c]);
        o0 = fmaf(rh3w[c],      hg, o0);
        o1 = fmaf(rh3w[64 + c], hg, o1);
    }
    float mu01 = sigm_f(o0 + rh3b[0]);
    float mu   = mu01 * 55.0f;
    float sg   = fmaxf(o1 + rh3b[1], 0.001f) * 55.0f;

    float ux, uy, uz;
    geom_f(pix >> 9, pix & 511, ux, uy, uz);
    float pxe = mu*ux*l2e[0] + mu*uy*l2e[4] + mu*uz*l2e[8]  + l2e[12];
    float pye = mu*ux*l2e[1] + mu*uy*l2e[5] + mu*uz*l2e[9]  + l2e[13];
    float rx = sigm_f(4.0f * ((pxe + 55.0f) * (1.0f/110.0f) - 0.5f));
    float ry = sigm_f(4.0f * ((pye + 55.0f) * (1.0f/110.0f) - 0.5f));

    refp[idx*2]     = rx;
    refp[idx*2 + 1] = ry;
    sigf[idx*2]     = sg;
    sigf[idx*2 + 1] = 1.0f / (sg + 1e-6f);
    out_mu[idx]     = mu01;
    out_sigma[idx]  = sg;
}

// ================= deformable attention sampler =================
__global__ void __launch_bounds__(256) k_msda(
    const float* __restrict__ v,      // [b][65536][128]
    const float* __restrict__ offaw,  // [b][16384][144]
    const float* __restrict__ ref,    // [b][16384][2]
    float* __restrict__ out)          // [b][16384][128]
{
    int gq = blockIdx.x*2 + (threadIdx.x >> 7);
    int t  = threadIdx.x & 127;
    int head = t >> 4, c = t & 15;
    int b = gq >> 14;
    const float* oa = offaw + (size_t)gq*144;
    float rx = ref[gq*2], ry = ref[gq*2 + 1];

    float lg[6];
    float mx = -1e30f;
    #pragma unroll
    for (int p = 0; p < 6; ++p){ lg[p] = oa[96 + head*6 + p]; mx = fmaxf(mx, lg[p]); }
    float den = 0.f;
    #pragma unroll
    for (int p = 0; p < 6; ++p){ lg[p] = expf(lg[p] - mx); den += lg[p]; }
    float iden = 1.f / den;

    const float* vb = v + (size_t)b*65536*128 + head*16 + c;
    float acc = 0.f;
    #pragma unroll
    for (int p = 0; p < 6; ++p){
        float ox = oa[(head*6 + p)*2 + 0];
        float oy = oa[(head*6 + p)*2 + 1];
        float xs = (rx + ox * (1.0f/256.0f)) * 256.0f - 0.5f;
        float ys = (ry + oy * (1.0f/256.0f)) * 256.0f - 0.5f;
        float x0f = floorf(xs), y0f = floorf(ys);
        float wx = xs - x0f, wy = ys - y0f;
        int x0 = (int)x0f, y0 = (int)y0f;
        float s = 0.f;
        #pragma unroll
        for (int dy = 0; dy < 2; ++dy){
            int yi = y0 + dy;
            bool vy = (yi >= 0) && (yi < 256);
            int yc = min(max(yi, 0), 255);
            float wyv = dy ? wy : (1.f - wy);
            #pragma unroll
            for (int dx = 0; dx < 2; ++dx){
                int xi = x0 + dx;
                bool vx = (xi >= 0) && (xi < 256);
                int xc = min(max(xi, 0), 255);
                float wv = wyv * (dx ? wx : (1.f - wx));
                if (vx && vy)
                    s = fmaf(vb[(size_t)(yc*256 + xc)*128], wv, s);
            }
        }
        acc = fmaf(lg[p]*iden, s, acc);
    }
    out[(size_t)gq*128 + t] = acc;
}

// ================= host launcher =================
extern "C" void kernel_launch(void* const* d_in, const int* in_sizes, int n_in,
                              void* d_out, int out_size)
{
    const float* x_rv  = (const float*)d_in[0];
    const float* bev   = (const float*)d_in[1];
    const float* l2e   = (const float*)d_in[2];
    const float* pq_w  = (const float*)d_in[3];
    const float* pq_b  = (const float*)d_in[4];
    const float* pv_w  = (const float*)d_in[5];
    const float* pv_b  = (const float*)d_in[6];
    const float* po_w  = (const float*)d_in[7];
    const float* po_b  = (const float*)d_in[8];
    const float* qs1_w = (const float*)d_in[9];
    const float* qs1_b = (const float*)d_in[10];
    const float* qs2_w = (const float*)d_in[11];
    const float* qs2_b = (const float*)d_in[12];
    const float* rh1_w = (const float*)d_in[13];
    const float* rh1_b = (const float*)d_in[14];
    const float* gn1_w = (const float*)d_in[15];
    const float* gn1_b = (const float*)d_in[16];
    const float* rh2_w = (const float*)d_in[17];
    const float* gn2_w = (const float*)d_in[18];
    const float* gn2_b = (const float*)d_in[19];
    const float* rh3_w = (const float*)d_in[20];
    const float* rh3_b = (const float*)d_in[21];
    const float* so_w  = (const float*)d_in[22];
    const float* so_b  = (const float*)d_in[23];
    const float* aw_w  = (const float*)d_in[24];
    const float* aw_b  = (const float*)d_in[25];
    const float* vp_w  = (const float*)d_in[26];
    const float* vp_b  = (const float*)d_in[27];
    const float* op_w  = (const float*)d_in[28];
    const float* op_b  = (const float*)d_in[29];

    float *wcombT, *bcomb, *woaT, *boa, *wyT, *by, *pqT, *rh1T, *qs1T, *rh2T,
          *vmap, *Q0, *t1, *t2, *stats, *refp, *sigf, *qt, *offaw, *attn;
    cudaGetSymbolAddress((void**)&wcombT, g_wcombT);
    cudaGetSymbolAddress((void**)&bcomb,  g_bcomb);
    cudaGetSymbolAddress((void**)&woaT,   g_woaT);
    cudaGetSymbolAddress((void**)&boa,    g_boa);
    cudaGetSymbolAddress((void**)&wyT,    g_wyT);
    cudaGetSymbolAddress((void**)&by,     g_by);
    cudaGetSymbolAddress((void**)&pqT,    g_pqT);
    cudaGetSymbolAddress((void**)&rh1T,   g_rh1T);
    cudaGetSymbolAddress((void**)&qs1T,   g_qs1T);
    cudaGetSymbolAddress((void**)&rh2T,   g_rh2T);
    cudaGetSymbolAddress((void**)&vmap,   g_v);
    cudaGetSymbolAddress((void**)&Q0,     g_Q0);
    cudaGetSymbolAddress((void**)&t1,     g_t1);
    cudaGetSymbolAddress((void**)&t2,     g_t2);
    cudaGetSymbolAddress((void**)&stats,  g_stats);
    cudaGetSymbolAddress((void**)&refp,   g_ref);
    cudaGetSymbolAddress((void**)&sigf,   g_sig);
    cudaGetSymbolAddress((void**)&qt,     g_qt);
    cudaGetSymbolAddress((void**)&offaw,  g_offaw);
    cudaGetSymbolAddress((void**)&attn,   g_attn);

    float* y_out     = (float*)d_out;                   // [4][128][16384] channel-major
    float* mu_out    = y_out + (size_t)4*128*16384;     // [4][16384]
    float* sigma_out = mu_out + 65536;                  // [4][16384]

    // dynamic smem: 2 A buffers (16*132 floats each) + 2 dup-W buffers (16*OT u64 each)
    const int dyn128 = 2*16*132*4 + 2*16*128*8;   // 49664 B
    const int dyn144 = 2*16*132*4 + 2*16*144*8;   // 53760 B
    cudaFuncSetAttribute(k_gemm4<128,128,1,0,0>, cudaFuncAttributeMaxDynamicSharedMemorySize, dyn128);
    cudaFuncSetAttribute(k_gemm4<128,128,0,0,0>, cudaFuncAttributeMaxDynamicSharedMemorySize, dyn128);
    cudaFuncSetAttribute(k_gemm4<131,128,2,1,0>, cudaFuncAttributeMaxDynamicSharedMemorySize, dyn128);
    cudaFuncSetAttribute(k_gemm4<130,128,3,0,1>, cudaFuncAttributeMaxDynamicSharedMemorySize, dyn128);
    cudaFuncSetAttribute(k_gemm4<128,144,0,0,0>, cudaFuncAttributeMaxDynamicSharedMemorySize, dyn144);
    cudaFuncSetAttribute(k_gemm4<256,128,4,1,0>, cudaFuncAttributeMaxDynamicSharedMemorySize, dyn128);

    // 1. weight folding + duplicated transposes
    k_prep<<<762, 256>>>(vp_w, pv_w, pv_b, vp_b, so_w, so_b, aw_w, aw_b,
                         qs2_w, qs2_b, po_w, po_b, op_w, op_b,
                         pq_w, rh1_w, qs1_w, rh2_w,
                         wcombT, bcomb, woaT, boa, wyT, by,
                         pqT, rh1T, qs1T, rh2T);
    // 2. value map (vp o pv)(bev), pixel-major
    k_gemm4<128,128,1,0,0><<<dim3(512,4), 256, dyn128>>>(bev, wcombT, bcomb, vmap, nullptr, 65536);
    // 3. Q0 = pq(x), pixel-major
    k_gemm4<128,128,0,0,0><<<dim3(128,4), 256, dyn128>>>(x_rv, pqT, pq_b, Q0, nullptr, 16384);
    // 4. rh1(concat(x, uvec)), channel-major
    k_gemm4<131,128,2,1,0><<<dim3(128,4), 256, dyn128>>>(x_rv, rh1T, rh1_b, t1, nullptr, 16384);
    // 5-6. gn1 + gelu
    k_gnstats<<<32, 512>>>(t1, stats, 16*16384);
    k_gnapply<<<8192, 256>>>(t1, stats, gn1_w, gn1_b);
    // 7. 3x3 wrap conv 128->64
    k_conv3<<<dim3(2,32,4), 256>>>(t1, rh2T, t2);
    // 8. gn2 stats
    k_gnstats<<<32, 512>>>(t2, stats + 64, 8*16384);
    // 9. head: gn2+gelu+rh3+geometry+refs+outputs
    k_head<<<256, 256>>>(t2, stats + 64, gn2_w, gn2_b, rh3_w, rh3_b, l2e,
                         mu_out, sigma_out, refp, sigf);
    // 10. qt = gelu(qs1(concat(Q0, sig_feat))), pixel-major
    k_gemm4<130,128,3,0,1><<<dim3(128,4), 256, dyn128>>>(Q0, qs1T, qs1_b, qt, sigf, 16384);
    // 11. offsets+logits straight from qt via folded (so/aw)@qs2
    k_gemm4<128,144,0,0,0><<<dim3(128,4), 288, dyn144>>>(qt, woaT, boa, offaw, nullptr, 16384);
    // 12. deformable attention gather
    k_msda<<<32768, 256>>>(vmap, offaw, refp, attn);
    // 13. y = (po@qs2) qt + (po@op) attn + b, channel-major straight into d_out
    k_gemm4<256,128,4,1,0><<<dim3(128,4), 256, dyn128>>>(qt, wyT, by, y_out, attn, 16384);
}

// round 14
// speedup vs baseline: 1.1737x; 1.1737x over previous
#include <cuda_runtime.h>
#include <math.h>

typedef unsigned long long u64;

// ================= constants =================
__constant__ float c_elev[32] = {
    -30.67f,-29.33f,-28.0f,-26.66f,-25.33f,-24.0f,-22.67f,-21.33f,
    -20.0f,-18.67f,-17.33f,-16.0f,-14.67f,-13.33f,-12.0f,-10.67f,
    -9.33f,-8.0f,-6.66f,-5.33f,-4.0f,-2.67f,-1.33f,0.0f,
    1.33f,2.67f,4.0f,5.33f,6.67f,8.0f,9.33f,10.67f};

// ================= scratch (no allocations allowed) =================
// transposed weights [k][o], zero-padded to 16-multiples in k (NOT duplicated)
__device__ __align__(16) float g_wcombT[128*128];
__device__ __align__(16) float g_bcomb[128];
__device__ __align__(16) float g_woaT[128*144];
__device__ __align__(16) float g_boa[144+4];
__device__ __align__(16) float g_wyT[256*128];
__device__ __align__(16) float g_by[128];
__device__ __align__(16) float g_pqT[128*128];
__device__ __align__(16) float g_rh1T[144*128];
__device__ __align__(16) float g_qs1T[144*128];
__device__ __align__(16) float g_rh2T[1152*64];
__device__ __align__(16) float g_v[(size_t)4*65536*128];
__device__ __align__(16) float g_Q0[(size_t)4*16384*128];
__device__ __align__(16) float g_t1[(size_t)4*128*16384];
__device__ __align__(16) float g_t2[(size_t)4*64*16384];
__device__ __align__(16) float g_stats[128];
__device__ __align__(16) float g_ref[4*16384*2];
__device__ __align__(16) float g_sig[4*16384*2];
__device__ __align__(16) float g_qt[(size_t)4*16384*128];
__device__ __align__(16) float g_offaw[(size_t)4*16384*144];
__device__ __align__(16) float g_attn[(size_t)4*16384*128];

// ================= f32x2 helpers =================
__device__ __forceinline__ u64 ffma2(u64 a, u64 b, u64 c){
    u64 d;
    asm("fma.rn.f32x2 %0, %1, %2, %3;" : "=l"(d) : "l"(a), "l"(b), "l"(c));
    return d;
}
__device__ __forceinline__ u64 add2(u64 a, u64 b){
    u64 d;
    asm("add.rn.f32x2 %0, %1, %2;" : "=l"(d) : "l"(a), "l"(b));
    return d;
}
__device__ __forceinline__ u64 splat2(float x){
    u64 d; unsigned int xi = __float_as_uint(x);
    asm("mov.b64 %0, {%1, %1};" : "=l"(d) : "r"(xi));
    return d;
}
__device__ __forceinline__ void unpack2(u64 v, float& lo, float& hi){
    unsigned int a, b;
    asm("mov.b64 {%0, %1}, %2;" : "=r"(a), "=r"(b) : "l"(v));
    lo = __uint_as_float(a); hi = __uint_as_float(b);
}

// ================= scalar helpers =================
__device__ __forceinline__ float gelu_f(float x){
    return 0.5f * x * (1.0f + erff(x * 0.7071067811865476f));
}
__device__ __forceinline__ float sigm_f(float x){
    return 1.0f / (1.0f + expf(-x));
}
__device__ __forceinline__ void geom_f(int h, int w, float& ux, float& uy, float& uz){
    float az = ((float)w - 256.0f) * (3.14159265358979323846f / 256.0f);
    float el = c_elev[31 - h] * 0.017453292519943295f;
    float sa, ca, se, ce;
    sincosf(az, &sa, &ca);
    sincosf(el, &se, &ce);
    ux = ca * ce; uy = sa * ce; uz = se;
}

// ================= weight folding + transposes (non-duplicated) =================
__global__ void __launch_bounds__(256) k_prep(
    const float* __restrict__ vp_w, const float* __restrict__ pv_w,
    const float* __restrict__ pv_b, const float* __restrict__ vp_b,
    const float* __restrict__ so_w, const float* __restrict__ so_b,
    const float* __restrict__ aw_w, const float* __restrict__ aw_b,
    const float* __restrict__ qs2_w, const float* __restrict__ qs2_b,
    const float* __restrict__ po_w, const float* __restrict__ po_b,
    const float* __restrict__ op_w, const float* __restrict__ op_b,
    const float* __restrict__ pq_w, const float* __restrict__ rh1_w,
    const float* __restrict__ qs1_w, const float* __restrict__ rh2_w,
    float* __restrict__ wcombT, float* __restrict__ bcomb,
    float* __restrict__ woaT, float* __restrict__ boa,
    float* __restrict__ wyT, float* __restrict__ by,
    float* __restrict__ pqT, float* __restrict__ rh1T,
    float* __restrict__ qs1T, float* __restrict__ rh2T)
{
    int t = blockIdx.x * 256 + threadIdx.x;
    if (t < 16384){
        int d = t >> 7, c = t & 127;
        float s = 0.f;
        #pragma unroll 8
        for (int o = 0; o < 128; ++o) s = fmaf(vp_w[d*128+o], pv_w[o*128+c], s);
        wcombT[c*128 + d] = s;
    } else if (t < 16512){
        int d = t - 16384;
        float s = vp_b[d];
        for (int o = 0; o < 128; ++o) s = fmaf(vp_w[d*128+o], pv_b[o], s);
        bcomb[d] = s;
    } else if (t < 34944){
        int i = t - 16512;
        int r = i >> 7, c = i & 127;
        const float* rw = (r < 96) ? (so_w + r*128) : (aw_w + (r-96)*128);
        float s = 0.f;
        #pragma unroll 8
        for (int o = 0; o < 128; ++o) s = fmaf(rw[o], qs2_w[o*128+c], s);
        woaT[c*144 + r] = s;
    } else if (t < 35088){
        int r = t - 34944;
        const float* rw = (r < 96) ? (so_w + r*128) : (aw_w + (r-96)*128);
        float s = (r < 96) ? so_b[r] : aw_b[r-96];
        for (int o = 0; o < 128; ++o) s = fmaf(rw[o], qs2_b[o], s);
        boa[r] = s;
    } else if (t < 67856){
        int i = t - 35088;
        int d = i >> 8, c = i & 255;
        const float* cw = (c < 128) ? (qs2_w + c) : (op_w + (c - 128));
        float s = 0.f;
        #pragma unroll 8
        for (int o = 0; o < 128; ++o) s = fmaf(po_w[d*128+o], cw[o*128], s);
        wyT[c*128 + d] = s;
    } else if (t < 67984){
        int d = t - 67856;
        float s = po_b[d];
        for (int o = 0; o < 128; ++o) s = fmaf(po_w[d*128+o], qs2_b[o] + op_b[o], s);
        by[d] = s;
    } else if (t < 84368){
        int i = t - 67984;
        int o = i >> 7, k = i & 127;
        pqT[k*128 + o] = pq_w[o*128 + k];
    } else if (t < 102800){
        int i = t - 84368;
        int k = i >> 7, o = i & 127;
        rh1T[k*128 + o] = (k < 131) ? rh1_w[o*131 + k] : 0.f;
    } else if (t < 121232){
        int i = t - 102800;
        int k = i >> 7, o = i & 127;
        qs1T[k*128 + o] = (k < 130) ? qs1_w[o*130 + k] : 0.f;
    } else if (t < 194960){
        int i = t - 121232;
        int r = i >> 6, o = i & 63;
        rh2T[r*64 + o] = rh2_w[o*1152 + r];
    }
}

// ====== occupancy-tuned f32x2 tile GEMM: 64 px x OT, output-pair accum ========
// WT k-major [NCH*16][OT], zero-padded. Per thread: 4 px x 8 outputs.
// AMODE: 0 pixel-major A[row][128]; 1 channel-major A[b][k][npix];
//        2 pixel-major + 3 geom ch (KTOT=131); 3 pixel-major + 2 aux ch (KTOT=130);
//        4 K=256: k<128 from A, k>=128 from aux (pixel-major)
// OMODE: 0 out [row][OT]; 1 out [b][o][npix]
// EPI:   0 bias; 1 bias+gelu
template<int KTOT, int OT, int AMODE, int OMODE, int EPI>
__global__ void __launch_bounds__(16*(OT/8), 3) k_gemm5(
    const float* __restrict__ A, const float* __restrict__ WT,
    const float* __restrict__ bias, float* __restrict__ out,
    const float* __restrict__ aux, int npix)
{
    constexpr int NT   = 16*(OT/8);
    constexpr int NCH  = (KTOT + 15) / 16;
    constexpr int AS   = 68;            // A row stride (floats), 16B-aligned rows
    constexpr int WROW = OT + 4;
    constexpr int NWLD = (4*OT) / NT;   // float4 W-loads per thread (=2)
    __shared__ float As[2][16*AS];
    __shared__ float Ws[2][16*WROW];

    const int b    = blockIdx.y;
    const int pix0 = blockIdx.x * 64;
    const int tid  = threadIdx.x;
    const int pxl  = (tid & 15) * 4;
    const int o0   = (tid >> 4) * 8;

    u64 acc[4][4];   // [px][output pair]
    #pragma unroll
    for (int i = 0; i < 4; ++i)
        #pragma unroll
        for (int j = 0; j < 4; ++j) acc[i][j] = 0ull;

    float4 aR, wR[NWLD];

    auto isTail = [&](int kc){
        return (AMODE == 2 || AMODE == 3) && (kc*16 + 16 > 128);
    };
    auto loadW = [&](int kc){
        const float* src = WT + (size_t)kc*16*OT;
        #pragma unroll
        for (int l = 0; l < NWLD; ++l){
            int i = tid + l*NT;
            wR[l] = *reinterpret_cast<const float4*>(src + i*4);
        }
    };
    auto storeW = [&](int buf){
        #pragma unroll
        for (int l = 0; l < NWLD; ++l){
            int i = tid + l*NT;
            int k = i / (OT/4), o4 = (i % (OT/4)) * 4;
            *reinterpret_cast<float4*>(&Ws[buf][k*WROW + o4]) = wR[l];
        }
    };
    auto loadA = [&](int kc){
        const int kbase = kc*16;
        if constexpr (AMODE == 1){
            int i = tid;
            if (NT == 256 || i < 256){
                int k = i >> 4, p4 = (i & 15) * 4;
                aR = *reinterpret_cast<const float4*>(
                    A + ((size_t)(b*KTOT + kbase + k))*(size_t)npix + pix0 + p4);
            }
        } else {
            const float* src = A; int koff = kbase;
            if constexpr (AMODE == 4){ if (kc >= 8){ src = aux; koff = kbase - 128; } }
            int i = tid;
            if (NT == 256 || i < 256){
                int px = i >> 2, q = i & 3;
                aR = *reinterpret_cast<const float4*>(
                    src + ((size_t)b*npix + pix0 + px)*128 + koff + q*4);
            }
        }
    };
    auto storeA = [&](int buf){
        int i = tid;
        if constexpr (AMODE == 1){
            if (NT == 256 || i < 256){
                int k = i >> 4, p4 = (i & 15) * 4;
                *reinterpret_cast<float4*>(&As[buf][k*AS + p4]) = aR;
            }
        } else {
            if (NT == 256 || i < 256){
                int px = i >> 2, q = i & 3;
                As[buf][(q*4+0)*AS + px] = aR.x;
                As[buf][(q*4+1)*AS + px] = aR.y;
                As[buf][(q*4+2)*AS + px] = aR.z;
                As[buf][(q*4+3)*AS + px] = aR.w;
            }
        }
    };
    auto tailFill = [&](int buf){
        constexpr int ZS = (AMODE == 2) ? 3 : 2;
        const float4 z4 = make_float4(0.f, 0.f, 0.f, 0.f);
        for (int i = tid; i < (16 - ZS)*16; i += NT){
            int k = ZS + (i >> 4), p4 = (i & 15) * 4;
            *reinterpret_cast<float4*>(&As[buf][k*AS + p4]) = z4;
        }
        if (tid < 64){
            if constexpr (AMODE == 2){
                int p = pix0 + tid;
                float ux, uy, uz; geom_f(p >> 9, p & 511, ux, uy, uz);
                As[buf][0*AS + tid] = ux;
                As[buf][1*AS + tid] = uy;
                As[buf][2*AS + tid] = uz;
            }
            if constexpr (AMODE == 3){
                const float2 s = *reinterpret_cast<const float2*>(
                    aux + ((size_t)b*npix + pix0 + tid)*2);
                As[buf][0*AS + tid] = s.x;
                As[buf][1*AS + tid] = s.y;
            }
        }
    };
    auto compute = [&](int buf){
        #pragma unroll
        for (int k = 0; k < 16; ++k){
            const float4 av = *reinterpret_cast<const float4*>(&As[buf][k*AS + pxl]);
            u64 as[4];
            as[0] = splat2(av.x); as[1] = splat2(av.y);
            as[2] = splat2(av.z); as[3] = splat2(av.w);
            const u64* wp = reinterpret_cast<const u64*>(&Ws[buf][k*WROW + o0]);
            const ulonglong2 w01 = *reinterpret_cast<const ulonglong2*>(wp);
            const ulonglong2 w23 = *reinterpret_cast<const ulonglong2*>(wp + 2);
            u64 w[4] = {w01.x, w01.y, w23.x, w23.y};
            #pragma unroll
            for (int px = 0; px < 4; ++px){
                acc[px][0] = ffma2(as[px], w[0], acc[px][0]);
                acc[px][1] = ffma2(as[px], w[1], acc[px][1]);
                acc[px][2] = ffma2(as[px], w[2], acc[px][2]);
                acc[px][3] = ffma2(as[px], w[3], acc[px][3]);
            }
        }
    };

    // prologue: fill buffer 0
    loadW(0);
    if (!isTail(0)) loadA(0);
    storeW(0);
    if (isTail(0)) tailFill(0); else storeA(0);
    __syncthreads();

    for (int kc = 0; kc < NCH; ++kc){
        const int cur = kc & 1, nxt = cur ^ 1;
        if (kc + 1 < NCH){
            loadW(kc + 1);
            if (!isTail(kc + 1)) loadA(kc + 1);
        }
        compute(cur);
        if (kc + 1 < NCH){
            storeW(nxt);
            if (isTail(kc + 1)) tailFill(nxt); else storeA(nxt);
            __syncthreads();
        }
    }

    // bias pairs
    u64 bp[4];
    {
        const u64* bq = reinterpret_cast<const u64*>(bias + o0);
        bp[0] = bq[0]; bp[1] = bq[1]; bp[2] = bq[2]; bp[3] = bq[3];
    }

    if constexpr (OMODE == 0){
        #pragma unroll
        for (int px = 0; px < 4; ++px){
            size_t row = (size_t)b*npix + pix0 + pxl + px;
            u64 v0 = add2(acc[px][0], bp[0]);
            u64 v1 = add2(acc[px][1], bp[1]);
            u64 v2 = add2(acc[px][2], bp[2]);
            u64 v3 = add2(acc[px][3], bp[3]);
            float* dst = out + row*(size_t)OT + o0;
            if constexpr (EPI == 1){
                float f[8];
                unpack2(v0, f[0], f[1]); unpack2(v1, f[2], f[3]);
                unpack2(v2, f[4], f[5]); unpack2(v3, f[6], f[7]);
                #pragma unroll
                for (int j = 0; j < 8; ++j) f[j] = gelu_f(f[j]);
                *reinterpret_cast<float4*>(dst)     = make_float4(f[0], f[1], f[2], f[3]);
                *reinterpret_cast<float4*>(dst + 4) = make_float4(f[4], f[5], f[6], f[7]);
            } else {
                ulonglong2 p0; p0.x = v0; p0.y = v1;
                ulonglong2 p1; p1.x = v2; p1.y = v3;
                *reinterpret_cast<ulonglong2*>(dst)     = p0;
                *reinterpret_cast<ulonglong2*>(dst + 4) = p1;
            }
        }
    } else {
        #pragma unroll
        for (int j = 0; j < 4; ++j){
            float ra[4], rb[4];
            #pragma unroll
            for (int px = 0; px < 4; ++px){
                u64 v = add2(acc[px][j], bp[j]);
                unpack2(v, ra[px], rb[px]);
            }
            float* d0 = out + ((size_t)(b*OT + o0 + 2*j))*(size_t)npix + pix0 + pxl;
            float* d1 = d0 + npix;
            *reinterpret_cast<float4*>(d0) = make_float4(ra[0], ra[1], ra[2], ra[3]);
            *reinterpret_cast<float4*>(d1) = make_float4(rb[0], rb[1], rb[2], rb[3]);
        }
    }
}

// ====== 3x3 conv, wrap pad (H=32,W=512), 128->64, f32x2 output pairs ==========
__global__ void __launch_bounds__(256, 2) k_conv3(
    const float* __restrict__ hin,  // [b][128][16384]
    const float* __restrict__ wtT,  // [1152][64] transposed
    float* __restrict__ out)        // [b][64][16384]
{
    __shared__ float In[24*260];
    __shared__ float Wc[72*68];
    const int b  = blockIdx.z;
    const int h  = blockIdx.y;
    const int w0 = blockIdx.x * 256;
    const int tid = threadIdx.x;
    const int pxl = (tid & 31) * 8;
    const int o0  = (tid >> 5) * 8;

    u64 acc[8][4];
    #pragma unroll
    for (int i = 0; i < 8; ++i)
        #pragma unroll
        for (int j = 0; j < 4; ++j) acc[i][j] = 0ull;

    float4 wR[5];
    auto loadW = [&](int icc){
        #pragma unroll
        for (int l = 0; l < 5; ++l){
            int i = tid + l*256;
            if (i < 1152)
                wR[l] = reinterpret_cast<const float4*>(wtT)[icc*1152 + i];
        }
    };

    loadW(0);
    for (int icc = 0; icc < 16; ++icc){
        __syncthreads();
        #pragma unroll
        for (int l = 0; l < 5; ++l){
            int i = tid + l*256;
            if (i < 1152){
                int r = i >> 4, o4 = (i & 15) * 4;
                *reinterpret_cast<float4*>(&Wc[r*68 + o4]) = wR[l];
            }
        }
        for (int i = tid; i < 24*258; i += 256){
            int r = i / 258, x = i - r*258;
            int ic = r / 3, ky = r - ic*3;
            int c  = icc*8 + ic;
            int hh = (h + ky + 31) & 31;
            int ww = (w0 + x - 1) & 511;
            In[r*260 + x] = hin[(((size_t)(b*128 + c)) << 14) + (hh << 9) + ww];
        }
        __syncthreads();
        if (icc + 1 < 16) loadW(icc + 1);
        #pragma unroll
        for (int ic = 0; ic < 8; ++ic){
            #pragma unroll
            for (int ky = 0; ky < 3; ++ky){
                const float* inr = &In[(ic*3 + ky)*260 + pxl];
                float a[12];
                *reinterpret_cast<float4*>(&a[0]) = *reinterpret_cast<const float4*>(inr);
                *reinterpret_cast<float4*>(&a[4]) = *reinterpret_cast<const float4*>(inr + 4);
                *reinterpret_cast<float4*>(&a[8]) = *reinterpret_cast<const float4*>(inr + 8);
                u64 as[10];
                #pragma unroll
                for (int x = 0; x < 10; ++x) as[x] = splat2(a[x]);
                #pragma unroll
                for (int kx = 0; kx < 3; ++kx){
                    const u64* wp = reinterpret_cast<const u64*>(
                        &Wc[(ic*9 + ky*3 + kx)*68 + o0]);
                    const ulonglong2 w01 = *reinterpret_cast<const ulonglong2*>(wp);
                    const ulonglong2 w23 = *reinterpret_cast<const ulonglong2*>(wp + 2);
                    u64 w[4] = {w01.x, w01.y, w23.x, w23.y};
                    #pragma unroll
                    for (int px = 0; px < 8; ++px){
                        acc[px][0] = ffma2(as[px+kx], w[0], acc[px][0]);
                        acc[px][1] = ffma2(as[px+kx], w[1], acc[px][1]);
                        acc[px][2] = ffma2(as[px+kx], w[2], acc[px][2]);
                        acc[px][3] = ffma2(as[px+kx], w[3], acc[px][3]);
                    }
                }
            }
        }
    }
    #pragma unroll
    for (int j = 0; j < 4; ++j){
        float ra[8], rb[8];
        #pragma unroll
        for (int px = 0; px < 8; ++px) unpack2(acc[px][j], ra[px], rb[px]);
        float* d0 = out + ((size_t)(b*64 + o0 + 2*j))*16384 + h*512 + w0 + pxl;
        float* d1 = d0 + 16384;
        *reinterpret_cast<float4*>(d0)     = make_float4(ra[0], ra[1], ra[2], ra[3]);
        *reinterpret_cast<float4*>(d0 + 4) = make_float4(ra[4], ra[5], ra[6], ra[7]);
        *reinterpret_cast<float4*>(d1)     = make_float4(rb[0], rb[1], rb[2], rb[3]);
        *reinterpret_cast<float4*>(d1 + 4) = make_float4(rb[4], rb[5], rb[6], rb[7]);
    }
}

// ================= group-norm statistics =================
__global__ void __launch_bounds__(512) k_gnstats(
    const float* __restrict__ x, float* __restrict__ st, int nper)
{
    __shared__ float sh[1024];
    size_t base = (size_t)blockIdx.x * (size_t)nper;
    float s = 0.f, sq = 0.f;
    const float4* xv = reinterpret_cast<const float4*>(x + base);
    int n4 = nper >> 2;
    for (int i = threadIdx.x; i < n4; i += 512){
        float4 v = xv[i];
        s  += v.x + v.y + v.z + v.w;
        sq += v.x*v.x + v.y*v.y + v.z*v.z + v.w*v.w;
    }
    sh[threadIdx.x] = s; sh[512 + threadIdx.x] = sq;
    __syncthreads();
    for (int off = 256; off > 0; off >>= 1){
        if (threadIdx.x < off){
            sh[threadIdx.x]       += sh[threadIdx.x + off];
            sh[512 + threadIdx.x] += sh[512 + threadIdx.x + off];
        }
        __syncthreads();
    }
    if (threadIdx.x == 0){
        float mean = sh[0] / (float)nper;
        float var  = sh[512] / (float)nper - mean*mean;
        st[blockIdx.x*2]     = mean;
        st[blockIdx.x*2 + 1] = rsqrtf(var + 1e-5f);
    }
}

// ================= gn1 apply + gelu, float4, in place =================
__global__ void __launch_bounds__(256) k_gnapply(
    float* __restrict__ x, const float* __restrict__ st,
    const float* __restrict__ gw, const float* __restrict__ gb)
{
    size_t i4 = (size_t)blockIdx.x*256 + threadIdx.x;
    size_t i  = i4 * 4;
    int c  = (int)((i >> 14) & 127);
    int bg = (int)(i >> 21) * 8 + (c >> 4);
    float m = st[bg*2], rs = st[bg*2 + 1];
    float w = gw[c], bb = gb[c];
    float4 v = reinterpret_cast<float4*>(x)[i4];
    v.x = gelu_f((v.x - m) * rs * w + bb);
    v.y = gelu_f((v.y - m) * rs * w + bb);
    v.z = gelu_f((v.z - m) * rs * w + bb);
    v.w = gelu_f((v.w - m) * rs * w + bb);
    reinterpret_cast<float4*>(x)[i4] = v;
}

// ================= gn2-apply + gelu + rh3 + geometry + refs =================
__global__ void __launch_bounds__(256) k_head(
    const float* __restrict__ t2, const float* __restrict__ st2,
    const float* __restrict__ g2w, const float* __restrict__ g2b,
    const float* __restrict__ rh3w, const float* __restrict__ rh3b,
    const float* __restrict__ l2e,
    float* __restrict__ out_mu, float* __restrict__ out_sigma,
    float* __restrict__ refp, float* __restrict__ sigf)
{
    int idx = blockIdx.x*256 + threadIdx.x;   // 0..65535
    int b = idx >> 14, pix = idx & 16383;
    float o0 = 0.f, o1 = 0.f;
    #pragma unroll 4
    for (int c = 0; c < 64; ++c){
        int bg = b*8 + (c >> 3);
        float m  = st2[bg*2], rs = st2[bg*2 + 1];
        float v  = t2[((size_t)(b*64 + c))*16384 + pix];
        float hg = gelu_f((v - m) * rs * g2w[c] + g2b[c]);
        o0 = fmaf(rh3w[c],      hg, o0);
        o1 = fmaf(rh3w[64 + c], hg, o1);
    }
    float mu01 = sigm_f(o0 + rh3b[0]);
    float mu   = mu01 * 55.0f;
    float sg   = fmaxf(o1 + rh3b[1], 0.001f) * 55.0f;

    float ux, uy, uz;
    geom_f(pix >> 9, pix & 511, ux, uy, uz);
    float pxe = mu*ux*l2e[0] + mu*uy*l2e[4] + mu*uz*l2e[8]  + l2e[12];
    float pye = mu*ux*l2e[1] + mu*uy*l2e[5] + mu*uz*l2e[9]  + l2e[13];
    float rx = sigm_f(4.0f * ((pxe + 55.0f) * (1.0f/110.0f) - 0.5f));
    float ry = sigm_f(4.0f * ((pye + 55.0f) * (1.0f/110.0f) - 0.5f));

    refp[idx*2]     = rx;
    refp[idx*2 + 1] = ry;
    sigf[idx*2]     = sg;
    sigf[idx*2 + 1] = 1.0f / (sg + 1e-6f);
    out_mu[idx]     = mu01;
    out_sigma[idx]  = sg;
}

// ================= deformable attention sampler =================
__global__ void __launch_bounds__(256) k_msda(
    const float* __restrict__ v,      // [b][65536][128]
    const float* __restrict__ offaw,  // [b][16384][144]
    const float* __restrict__ ref,    // [b][16384][2]
    float* __restrict__ out)          // [b][16384][128]
{
    int gq = blockIdx.x*2 + (threadIdx.x >> 7);
    int t  = threadIdx.x & 127;
    int head = t >> 4, c = t & 15;
    int b = gq >> 14;
    const float* oa = offaw + (size_t)gq*144;
    float rx = ref[gq*2], ry = ref[gq*2 + 1];

    float lg[6];
    float mx = -1e30f;
    #pragma unroll
    for (int p = 0; p < 6; ++p){ lg[p] = oa[96 + head*6 + p]; mx = fmaxf(mx, lg[p]); }
    float den = 0.f;
    #pragma unroll
    for (int p = 0; p < 6; ++p){ lg[p] = expf(lg[p] - mx); den += lg[p]; }
    float iden = 1.f / den;

    const float* vb = v + (size_t)b*65536*128 + head*16 + c;
    float acc = 0.f;
    #pragma unroll
    for (int p = 0; p < 6; ++p){
        float ox = oa[(head*6 + p)*2 + 0];
        float oy = oa[(head*6 + p)*2 + 1];
        float xs = (rx + ox * (1.0f/256.0f)) * 256.0f - 0.5f;
        float ys = (ry + oy * (1.0f/256.0f)) * 256.0f - 0.5f;
        float x0f = floorf(xs), y0f = floorf(ys);
        float wx = xs - x0f, wy = ys - y0f;
        int x0 = (int)x0f, y0 = (int)y0f;
        float s = 0.f;
        #pragma unroll
        for (int dy = 0; dy < 2; ++dy){
            int yi = y0 + dy;
            bool vy = (yi >= 0) && (yi < 256);
            int yc = min(max(yi, 0), 255);
            float wyv = dy ? wy : (1.f - wy);
            #pragma unroll
            for (int dx = 0; dx < 2; ++dx){
                int xi = x0 + dx;
                bool vx = (xi >= 0) && (xi < 256);
                int xc = min(max(xi, 0), 255);
                float wv = wyv * (dx ? wx : (1.f - wx));
                if (vx && vy)
                    s = fmaf(vb[(size_t)(yc*256 + xc)*128], wv, s);
            }
        }
        acc = fmaf(lg[p]*iden, s, acc);
    }
    out[(size_t)gq*128 + t] = acc;
}

// ================= host launcher =================
extern "C" void kernel_launch(void* const* d_in, const int* in_sizes, int n_in,
                              void* d_out, int out_size)
{
    const float* x_rv  = (const float*)d_in[0];
    const float* bev   = (const float*)d_in[1];
    const float* l2e   = (const float*)d_in[2];
    const float* pq_w  = (const float*)d_in[3];
    const float* pq_b  = (const float*)d_in[4];
    const float* pv_w  = (const float*)d_in[5];
    const float* pv_b  = (const float*)d_in[6];
    const float* po_w  = (const float*)d_in[7];
    const float* po_b  = (const float*)d_in[8];
    const float* qs1_w = (const float*)d_in[9];
    const float* qs1_b = (const float*)d_in[10];
    const float* qs2_w = (const float*)d_in[11];
    const float* qs2_b = (const float*)d_in[12];
    const float* rh1_w = (const float*)d_in[13];
    const float* rh1_b = (const float*)d_in[14];
    const float* gn1_w = (const float*)d_in[15];
    const float* gn1_b = (const float*)d_in[16];
    const float* rh2_w = (const float*)d_in[17];
    const float* gn2_w = (const float*)d_in[18];
    const float* gn2_b = (const float*)d_in[19];
    const float* rh3_w = (const float*)d_in[20];
    const float* rh3_b = (const float*)d_in[21];
    const float* so_w  = (const float*)d_in[22];
    const float* so_b  = (const float*)d_in[23];
    const float* aw_w  = (const float*)d_in[24];
    const float* aw_b  = (const float*)d_in[25];
    const float* vp_w  = (const float*)d_in[26];
    const float* vp_b  = (const float*)d_in[27];
    const float* op_w  = (const float*)d_in[28];
    const float* op_b  = (const float*)d_in[29];

    float *wcombT, *bcomb, *woaT, *boa, *wyT, *by, *pqT, *rh1T, *qs1T, *rh2T,
          *vmap, *Q0, *t1, *t2, *stats, *refp, *sigf, *qt, *offaw, *attn;
    cudaGetSymbolAddress((void**)&wcombT, g_wcombT);
    cudaGetSymbolAddress((void**)&bcomb,  g_bcomb);
    cudaGetSymbolAddress((void**)&woaT,   g_woaT);
    cudaGetSymbolAddress((void**)&boa,    g_boa);
    cudaGetSymbolAddress((void**)&wyT,    g_wyT);
    cudaGetSymbolAddress((void**)&by,     g_by);
    cudaGetSymbolAddress((void**)&pqT,    g_pqT);
    cudaGetSymbolAddress((void**)&rh1T,   g_rh1T);
    cudaGetSymbolAddress((void**)&qs1T,   g_qs1T);
    cudaGetSymbolAddress((void**)&rh2T,   g_rh2T);
    cudaGetSymbolAddress((void**)&vmap,   g_v);
    cudaGetSymbolAddress((void**)&Q0,     g_Q0);
    cudaGetSymbolAddress((void**)&t1,     g_t1);
    cudaGetSymbolAddress((void**)&t2,     g_t2);
    cudaGetSymbolAddress((void**)&stats,  g_stats);
    cudaGetSymbolAddress((void**)&refp,   g_ref);
    cudaGetSymbolAddress((void**)&sigf,   g_sig);
    cudaGetSymbolAddress((void**)&qt,     g_qt);
    cudaGetSymbolAddress((void**)&offaw,  g_offaw);
    cudaGetSymbolAddress((void**)&attn,   g_attn);

    float* y_out     = (float*)d_out;                   // [4][128][16384] channel-major
    float* mu_out    = y_out + (size_t)4*128*16384;     // [4][16384]
    float* sigma_out = mu_out + 65536;                  // [4][16384]

    // 1. weight folding + transposes
    k_prep<<<762, 256>>>(vp_w, pv_w, pv_b, vp_b, so_w, so_b, aw_w, aw_b,
                         qs2_w, qs2_b, po_w, po_b, op_w, op_b,
                         pq_w, rh1_w, qs1_w, rh2_w,
                         wcombT, bcomb, woaT, boa, wyT, by,
                         pqT, rh1T, qs1T, rh2T);
    // 2. value map (vp o pv)(bev), pixel-major
    k_gemm5<128,128,1,0,0><<<dim3(1024,4), 256>>>(bev, wcombT, bcomb, vmap, nullptr, 65536);
    // 3. Q0 = pq(x), pixel-major
    k_gemm5<128,128,0,0,0><<<dim3(256,4), 256>>>(x_rv, pqT, pq_b, Q0, nullptr, 16384);
    // 4. rh1(concat(x, uvec)), channel-major
    k_gemm5<131,128,2,1,0><<<dim3(256,4), 256>>>(x_rv, rh1T, rh1_b, t1, nullptr, 16384);
    // 5-6. gn1 + gelu
    k_gnstats<<<32, 512>>>(t1, stats, 16*16384);
    k_gnapply<<<8192, 256>>>(t1, stats, gn1_w, gn1_b);
    // 7. 3x3 wrap conv 128->64
    k_conv3<<<dim3(2,32,4), 256>>>(t1, rh2T, t2);
    // 8. gn2 stats
    k_gnstats<<<32, 512>>>(t2, stats + 64, 8*16384);
    // 9. head: gn2+gelu+rh3+geometry+refs+outputs
    k_head<<<256, 256>>>(t2, stats + 64, gn2_w, gn2_b, rh3_w, rh3_b, l2e,
                         mu_out, sigma_out, refp, sigf);
    // 10. qt = gelu(qs1(concat(Q0, sig_feat))), pixel-major
    k_gemm5<130,128,3,0,1><<<dim3(256,4), 256>>>(Q0, qs1T, qs1_b, qt, sigf, 16384);
    // 11. offsets+logits straight from qt via folded (so/aw)@qs2
    k_gemm5<128,144,0,0,0><<<dim3(256,4), 288>>>(qt, woaT, boa, offaw, nullptr, 16384);
    // 12. deformable attention gather
    k_msda<<<32768, 256>>>(vmap, offaw, refp, attn);
    // 13. y = (po@qs2) qt + (po@op) attn + b, channel-major straight into d_out
    k_gemm5<256,128,4,1,0><<<dim3(256,4), 256>>>(qt, wyT, by, y_out, attn, 16384);
}

// round 15
// speedup vs baseline: 1.2569x; 1.0709x over previous
#include <cuda_runtime.h>
#include <math.h>

typedef unsigned long long u64;

// ================= constants =================
__constant__ float c_elev[32] = {
    -30.67f,-29.33f,-28.0f,-26.66f,-25.33f,-24.0f,-22.67f,-21.33f,
    -20.0f,-18.67f,-17.33f,-16.0f,-14.67f,-13.33f,-12.0f,-10.67f,
    -9.33f,-8.0f,-6.66f,-5.33f,-4.0f,-2.67f,-1.33f,0.0f,
    1.33f,2.67f,4.0f,5.33f,6.67f,8.0f,9.33f,10.67f};

// ================= scratch (no allocations allowed) =================
// transposed weights [k][o], zero-padded to 16-multiples in k
__device__ __align__(16) float g_wcombT[128*128];
__device__ __align__(16) float g_bcomb[128];
__device__ __align__(16) float g_woaT[128*144];
__device__ __align__(16) float g_boa[144+4];
__device__ __align__(16) float g_wyT[256*128];
__device__ __align__(16) float g_by[128];
__device__ __align__(16) float g_pqT[128*128];
__device__ __align__(16) float g_rh1T[144*128];
__device__ __align__(16) float g_qs1T[144*128];   // now holds (qs1[:,:128]@pq_w)^T + sig rows
__device__ __align__(16) float g_bqs1[128];       // folded qs1 bias
__device__ __align__(16) float g_rh2T[1152*64];
__device__ __align__(16) float g_v[(size_t)4*65536*128];
__device__ __align__(16) float g_t1[(size_t)4*128*16384];
__device__ __align__(16) float g_t2[(size_t)4*64*16384];
__device__ __align__(16) float g_stats[128];
__device__ __align__(16) float g_part[1024];      // two-stage GN partials (512 pairs)
__device__ __align__(16) float g_ref[4*16384*2];
__device__ __align__(16) float g_sig[4*16384*2];
__device__ __align__(16) float g_qt[(size_t)4*16384*128];
__device__ __align__(16) float g_offaw[(size_t)4*16384*144];
__device__ __align__(16) float g_attn[(size_t)4*16384*128];

// ================= f32x2 helpers =================
__device__ __forceinline__ u64 ffma2(u64 a, u64 b, u64 c){
    u64 d;
    asm("fma.rn.f32x2 %0, %1, %2, %3;" : "=l"(d) : "l"(a), "l"(b), "l"(c));
    return d;
}
__device__ __forceinline__ u64 add2(u64 a, u64 b){
    u64 d;
    asm("add.rn.f32x2 %0, %1, %2;" : "=l"(d) : "l"(a), "l"(b));
    return d;
}
__device__ __forceinline__ u64 splat2(float x){
    u64 d; unsigned int xi = __float_as_uint(x);
    asm("mov.b64 %0, {%1, %1};" : "=l"(d) : "r"(xi));
    return d;
}
__device__ __forceinline__ void unpack2(u64 v, float& lo, float& hi){
    unsigned int a, b;
    asm("mov.b64 {%0, %1}, %2;" : "=r"(a), "=r"(b) : "l"(v));
    lo = __uint_as_float(a); hi = __uint_as_float(b);
}

// ================= scalar helpers =================
__device__ __forceinline__ float gelu_f(float x){
    return 0.5f * x * (1.0f + erff(x * 0.7071067811865476f));
}
__device__ __forceinline__ float sigm_f(float x){
    return 1.0f / (1.0f + expf(-x));
}
__device__ __forceinline__ void geom_f(int h, int w, float& ux, float& uy, float& uz){
    float az = ((float)w - 256.0f) * (3.14159265358979323846f / 256.0f);
    float el = c_elev[31 - h] * 0.017453292519943295f;
    float sa, ca, se, ce;
    sincosf(az, &sa, &ca);
    sincosf(el, &se, &ce);
    ux = ca * ce; uy = sa * ce; uz = se;
}

// ================= weight folding + transposes =================
__global__ void __launch_bounds__(256) k_prep(
    const float* __restrict__ vp_w, const float* __restrict__ pv_w,
    const float* __restrict__ pv_b, const float* __restrict__ vp_b,
    const float* __restrict__ so_w, const float* __restrict__ so_b,
    const float* __restrict__ aw_w, const float* __restrict__ aw_b,
    const float* __restrict__ qs2_w, const float* __restrict__ qs2_b,
    const float* __restrict__ po_w, const float* __restrict__ po_b,
    const float* __restrict__ op_w, const float* __restrict__ op_b,
    const float* __restrict__ pq_w, const float* __restrict__ pq_b,
    const float* __restrict__ rh1_w,
    const float* __restrict__ qs1_w, const float* __restrict__ qs1_b,
    const float* __restrict__ rh2_w,
    float* __restrict__ wcombT, float* __restrict__ bcomb,
    float* __restrict__ woaT, float* __restrict__ boa,
    float* __restrict__ wyT, float* __restrict__ by,
    float* __restrict__ pqT, float* __restrict__ rh1T,
    float* __restrict__ qs1T, float* __restrict__ bqs1,
    float* __restrict__ rh2T)
{
    int t = blockIdx.x * 256 + threadIdx.x;
    if (t < 16384){
        int d = t >> 7, c = t & 127;
        float s = 0.f;
        #pragma unroll 8
        for (int o = 0; o < 128; ++o) s = fmaf(vp_w[d*128+o], pv_w[o*128+c], s);
        wcombT[c*128 + d] = s;
    } else if (t < 16512){
        int d = t - 16384;
        float s = vp_b[d];
        for (int o = 0; o < 128; ++o) s = fmaf(vp_w[d*128+o], pv_b[o], s);
        bcomb[d] = s;
    } else if (t < 34944){
        int i = t - 16512;
        int r = i >> 7, c = i & 127;
        const float* rw = (r < 96) ? (so_w + r*128) : (aw_w + (r-96)*128);
        float s = 0.f;
        #pragma unroll 8
        for (int o = 0; o < 128; ++o) s = fmaf(rw[o], qs2_w[o*128+c], s);
        woaT[c*144 + r] = s;
    } else if (t < 35088){
        int r = t - 34944;
        const float* rw = (r < 96) ? (so_w + r*128) : (aw_w + (r-96)*128);
        float s = (r < 96) ? so_b[r] : aw_b[r-96];
        for (int o = 0; o < 128; ++o) s = fmaf(rw[o], qs2_b[o], s);
        boa[r] = s;
    } else if (t < 67856){
        int i = t - 35088;
        int d = i >> 8, c = i & 255;
        const float* cw = (c < 128) ? (qs2_w + c) : (op_w + (c - 128));
        float s = 0.f;
        #pragma unroll 8
        for (int o = 0; o < 128; ++o) s = fmaf(po_w[d*128+o], cw[o*128], s);
        wyT[c*128 + d] = s;
    } else if (t < 67984){
        int d = t - 67856;
        float s = po_b[d];
        for (int o = 0; o < 128; ++o) s = fmaf(po_w[d*128+o], qs2_b[o] + op_b[o], s);
        by[d] = s;
    } else if (t < 84368){
        int i = t - 67984;
        int o = i >> 7, k = i & 127;
        pqT[k*128 + o] = pq_w[o*128 + k];
    } else if (t < 102800){
        int i = t - 84368;
        int k = i >> 7, o = i & 127;
        rh1T[k*128 + o] = (k < 131) ? rh1_w[o*131 + k] : 0.f;
    } else if (t < 121232){
        // qs1T fold: k<128 -> (qs1[:, :128] @ pq_w)^T ; k=128,129 -> sig weights; else 0
        int i = t - 102800;
        int k = i >> 7, o = i & 127;
        float s;
        if (k < 128){
            s = 0.f;
            #pragma unroll 8
            for (int c = 0; c < 128; ++c) s = fmaf(qs1_w[o*130 + c], pq_w[c*128 + k], s);
        } else if (k < 130){
            s = qs1_w[o*130 + k];
        } else {
            s = 0.f;
        }
        qs1T[k*128 + o] = s;
    } else if (t < 121360){
        // folded qs1 bias: qs1_b + qs1[:, :128] @ pq_b
        int o = t - 121232;
        float s = qs1_b[o];
        for (int c = 0; c < 128; ++c) s = fmaf(qs1_w[o*130 + c], pq_b[c], s);
        bqs1[o] = s;
    } else if (t < 195088){
        int i = t - 121360;
        int r = i >> 6, o = i & 63;
        rh2T[r*64 + o] = rh2_w[o*1152 + r];
    }
}

// ====== occupancy-tuned f32x2 tile GEMM: 64 px x OT, output-pair accum ========
// WT k-major [NCH*16][OT], zero-padded. Per thread: 4 px x 8 outputs.
// AMODE: 0 pixel-major A[row][128]; 1 channel-major A[b][k][npix];
//        2 pixel-major + 3 geom ch (KTOT=131); 3 pixel-major + 2 aux ch (KTOT=130);
//        4 K=256: k<128 from A, k>=128 from aux (pixel-major)
// OMODE: 0 out [row][OT]; 1 out [b][o][npix]
// EPI:   0 bias; 1 bias+gelu
template<int KTOT, int OT, int AMODE, int OMODE, int EPI>
__global__ void __launch_bounds__(16*(OT/8), 3) k_gemm5(
    const float* __restrict__ A, const float* __restrict__ WT,
    const float* __restrict__ bias, float* __restrict__ out,
    const float* __restrict__ aux, int npix)
{
    constexpr int NT   = 16*(OT/8);
    constexpr int NCH  = (KTOT + 15) / 16;
    constexpr int AS   = 68;
    constexpr int WROW = OT + 4;
    constexpr int NWLD = (4*OT) / NT;
    __shared__ float As[2][16*AS];
    __shared__ float Ws[2][16*WROW];

    const int b    = blockIdx.y;
    const int pix0 = blockIdx.x * 64;
    const int tid  = threadIdx.x;
    const int pxl  = (tid & 15) * 4;
    const int o0   = (tid >> 4) * 8;

    u64 acc[4][4];
    #pragma unroll
    for (int i = 0; i < 4; ++i)
        #pragma unroll
        for (int j = 0; j < 4; ++j) acc[i][j] = 0ull;

    float4 aR, wR[NWLD];

    auto isTail = [&](int kc){
        return (AMODE == 2 || AMODE == 3) && (kc*16 + 16 > 128);
    };
    auto loadW = [&](int kc){
        const float* src = WT + (size_t)kc*16*OT;
        #pragma unroll
        for (int l = 0; l < NWLD; ++l){
            int i = tid + l*NT;
            wR[l] = *reinterpret_cast<const float4*>(src + i*4);
        }
    };
    auto storeW = [&](int buf){
        #pragma unroll
        for (int l = 0; l < NWLD; ++l){
            int i = tid + l*NT;
            int k = i / (OT/4), o4 = (i % (OT/4)) * 4;
            *reinterpret_cast<float4*>(&Ws[buf][k*WROW + o4]) = wR[l];
        }
    };
    auto loadA = [&](int kc){
        const int kbase = kc*16;
        if constexpr (AMODE == 1){
            int i = tid;
            if (NT == 256 || i < 256){
                int k = i >> 4, p4 = (i & 15) * 4;
                aR = *reinterpret_cast<const float4*>(
                    A + ((size_t)(b*KTOT + kbase + k))*(size_t)npix + pix0 + p4);
            }
        } else {
            const float* src = A; int koff = kbase;
            if constexpr (AMODE == 4){ if (kc >= 8){ src = aux; koff = kbase - 128; } }
            int i = tid;
            if (NT == 256 || i < 256){
                int px = i >> 2, q = i & 3;
                aR = *reinterpret_cast<const float4*>(
                    src + ((size_t)b*npix + pix0 + px)*128 + koff + q*4);
            }
        }
    };
    auto storeA = [&](int buf){
        int i = tid;
        if constexpr (AMODE == 1){
            if (NT == 256 || i < 256){
                int k = i >> 4, p4 = (i & 15) * 4;
                *reinterpret_cast<float4*>(&As[buf][k*AS + p4]) = aR;
            }
        } else {
            if (NT == 256 || i < 256){
                int px = i >> 2, q = i & 3;
                As[buf][(q*4+0)*AS + px] = aR.x;
                As[buf][(q*4+1)*AS + px] = aR.y;
                As[buf][(q*4+2)*AS + px] = aR.z;
                As[buf][(q*4+3)*AS + px] = aR.w;
            }
        }
    };
    auto tailFill = [&](int buf){
        constexpr int ZS = (AMODE == 2) ? 3 : 2;
        const float4 z4 = make_float4(0.f, 0.f, 0.f, 0.f);
        for (int i = tid; i < (16 - ZS)*16; i += NT){
            int k = ZS + (i >> 4), p4 = (i & 15) * 4;
            *reinterpret_cast<float4*>(&As[buf][k*AS + p4]) = z4;
        }
        if (tid < 64){
            if constexpr (AMODE == 2){
                int p = pix0 + tid;
                float ux, uy, uz; geom_f(p >> 9, p & 511, ux, uy, uz);
                As[buf][0*AS + tid] = ux;
                As[buf][1*AS + tid] = uy;
                As[buf][2*AS + tid] = uz;
            }
            if constexpr (AMODE == 3){
                const float2 s = *reinterpret_cast<const float2*>(
                    aux + ((size_t)b*npix + pix0 + tid)*2);
                As[buf][0*AS + tid] = s.x;
                As[buf][1*AS + tid] = s.y;
            }
        }
    };
    auto compute = [&](int buf){
        #pragma unroll
        for (int k = 0; k < 16; ++k){
            const float4 av = *reinterpret_cast<const float4*>(&As[buf][k*AS + pxl]);
            u64 as[4];
            as[0] = splat2(av.x); as[1] = splat2(av.y);
            as[2] = splat2(av.z); as[3] = splat2(av.w);
            const u64* wp = reinterpret_cast<const u64*>(&Ws[buf][k*WROW + o0]);
            const ulonglong2 w01 = *reinterpret_cast<const ulonglong2*>(wp);
            const ulonglong2 w23 = *reinterpret_cast<const ulonglong2*>(wp + 2);
            u64 w[4] = {w01.x, w01.y, w23.x, w23.y};
            #pragma unroll
            for (int px = 0; px < 4; ++px){
                acc[px][0] = ffma2(as[px], w[0], acc[px][0]);
                acc[px][1] = ffma2(as[px], w[1], acc[px][1]);
                acc[px][2] = ffma2(as[px], w[2], acc[px][2]);
                acc[px][3] = ffma2(as[px], w[3], acc[px][3]);
            }
        }
    };

    loadW(0);
    if (!isTail(0)) loadA(0);
    storeW(0);
    if (isTail(0)) tailFill(0); else storeA(0);
    __syncthreads();

    for (int kc = 0; kc < NCH; ++kc){
        const int cur = kc & 1, nxt = cur ^ 1;
        if (kc + 1 < NCH){
            loadW(kc + 1);
            if (!isTail(kc + 1)) loadA(kc + 1);
        }
        compute(cur);
        if (kc + 1 < NCH){
            storeW(nxt);
            if (isTail(kc + 1)) tailFill(nxt); else storeA(nxt);
            __syncthreads();
        }
    }

    u64 bp[4];
    {
        const u64* bq = reinterpret_cast<const u64*>(bias + o0);
        bp[0] = bq[0]; bp[1] = bq[1]; bp[2] = bq[2]; bp[3] = bq[3];
    }

    if constexpr (OMODE == 0){
        #pragma unroll
        for (int px = 0; px < 4; ++px){
            size_t row = (size_t)b*npix + pix0 + pxl + px;
            u64 v0 = add2(acc[px][0], bp[0]);
            u64 v1 = add2(acc[px][1], bp[1]);
            u64 v2 = add2(acc[px][2], bp[2]);
            u64 v3 = add2(acc[px][3], bp[3]);
            float* dst = out + row*(size_t)OT + o0;
            if constexpr (EPI == 1){
                float f[8];
                unpack2(v0, f[0], f[1]); unpack2(v1, f[2], f[3]);
                unpack2(v2, f[4], f[5]); unpack2(v3, f[6], f[7]);
                #pragma unroll
                for (int j = 0; j < 8; ++j) f[j] = gelu_f(f[j]);
                *reinterpret_cast<float4*>(dst)     = make_float4(f[0], f[1], f[2], f[3]);
                *reinterpret_cast<float4*>(dst + 4) = make_float4(f[4], f[5], f[6], f[7]);
            } else {
                ulonglong2 p0; p0.x = v0; p0.y = v1;
                ulonglong2 p1; p1.x = v2; p1.y = v3;
                *reinterpret_cast<ulonglong2*>(dst)     = p0;
                *reinterpret_cast<ulonglong2*>(dst + 4) = p1;
            }
        }
    } else {
        #pragma unroll
        for (int j = 0; j < 4; ++j){
            float ra[4], rb[4];
            #pragma unroll
            for (int px = 0; px < 4; ++px){
                u64 v = add2(acc[px][j], bp[j]);
                unpack2(v, ra[px], rb[px]);
            }
            float* d0 = out + ((size_t)(b*OT + o0 + 2*j))*(size_t)npix + pix0 + pxl;
            float* d1 = d0 + npix;
            *reinterpret_cast<float4*>(d0) = make_float4(ra[0], ra[1], ra[2], ra[3]);
            *reinterpret_cast<float4*>(d1) = make_float4(rb[0], rb[1], rb[2], rb[3]);
        }
    }
}

// ====== 3x3 conv, wrap pad (H=32,W=512), 128->64, f32x2 output pairs ==========
__global__ void __launch_bounds__(256, 2) k_conv3(
    const float* __restrict__ hin,  // [b][128][16384]
    const float* __restrict__ wtT,  // [1152][64] transposed
    float* __restrict__ out)        // [b][64][16384]
{
    __shared__ float In[24*260];
    __shared__ float Wc[72*68];
    const int b  = blockIdx.z;
    const int h  = blockIdx.y;
    const int w0 = blockIdx.x * 256;
    const int tid = threadIdx.x;
    const int pxl = (tid & 31) * 8;
    const int o0  = (tid >> 5) * 8;

    u64 acc[8][4];
    #pragma unroll
    for (int i = 0; i < 8; ++i)
        #pragma unroll
        for (int j = 0; j < 4; ++j) acc[i][j] = 0ull;

    float4 wR[5];
    auto loadW = [&](int icc){
        #pragma unroll
        for (int l = 0; l < 5; ++l){
            int i = tid + l*256;
            if (i < 1152)
                wR[l] = reinterpret_cast<const float4*>(wtT)[icc*1152 + i];
        }
    };

    loadW(0);
    for (int icc = 0; icc < 16; ++icc){
        __syncthreads();
        #pragma unroll
        for (int l = 0; l < 5; ++l){
            int i = tid + l*256;
            if (i < 1152){
                int r = i >> 4, o4 = (i & 15) * 4;
                *reinterpret_cast<float4*>(&Wc[r*68 + o4]) = wR[l];
            }
        }
        for (int i = tid; i < 24*258; i += 256){
            int r = i / 258, x = i - r*258;
            int ic = r / 3, ky = r - ic*3;
            int c  = icc*8 + ic;
            int hh = (h + ky + 31) & 31;
            int ww = (w0 + x - 1) & 511;
            In[r*260 + x] = hin[(((size_t)(b*128 + c)) << 14) + (hh << 9) + ww];
        }
        __syncthreads();
        if (icc + 1 < 16) loadW(icc + 1);
        #pragma unroll
        for (int ic = 0; ic < 8; ++ic){
            #pragma unroll
            for (int ky = 0; ky < 3; ++ky){
                const float* inr = &In[(ic*3 + ky)*260 + pxl];
                float a[12];
                *reinterpret_cast<float4*>(&a[0]) = *reinterpret_cast<const float4*>(inr);
                *reinterpret_cast<float4*>(&a[4]) = *reinterpret_cast<const float4*>(inr + 4);
                *reinterpret_cast<float4*>(&a[8]) = *reinterpret_cast<const float4*>(inr + 8);
                u64 as[10];
                #pragma unroll
                for (int x = 0; x < 10; ++x) as[x] = splat2(a[x]);
                #pragma unroll
                for (int kx = 0; kx < 3; ++kx){
                    const u64* wp = reinterpret_cast<const u64*>(
                        &Wc[(ic*9 + ky*3 + kx)*68 + o0]);
                    const ulonglong2 w01 = *reinterpret_cast<const ulonglong2*>(wp);
                    const ulonglong2 w23 = *reinterpret_cast<const ulonglong2*>(wp + 2);
                    u64 w[4] = {w01.x, w01.y, w23.x, w23.y};
                    #pragma unroll
                    for (int px = 0; px < 8; ++px){
                        acc[px][0] = ffma2(as[px+kx], w[0], acc[px][0]);
                        acc[px][1] = ffma2(as[px+kx], w[1], acc[px][1]);
                        acc[px][2] = ffma2(as[px+kx], w[2], acc[px][2]);
                        acc[px][3] = ffma2(as[px+kx], w[3], acc[px][3]);
                    }
                }
            }
        }
    }
    #pragma unroll
    for (int j = 0; j < 4; ++j){
        float ra[8], rb[8];
        #pragma unroll
        for (int px = 0; px < 8; ++px) unpack2(acc[px][j], ra[px], rb[px]);
        float* d0 = out + ((size_t)(b*64 + o0 + 2*j))*16384 + h*512 + w0 + pxl;
        float* d1 = d0 + 16384;
        *reinterpret_cast<float4*>(d0)     = make_float4(ra[0], ra[1], ra[2], ra[3]);
        *reinterpret_cast<float4*>(d0 + 4) = make_float4(ra[4], ra[5], ra[6], ra[7]);
        *reinterpret_cast<float4*>(d1)     = make_float4(rb[0], rb[1], rb[2], rb[3]);
        *reinterpret_cast<float4*>(d1 + 4) = make_float4(rb[4], rb[5], rb[6], rb[7]);
    }
}

// ============ two-stage group-norm statistics (deterministic) =================
// stage 1: 16 blocks per group, each reduces a contiguous 1/16 span
__global__ void __launch_bounds__(256) k_gnstats1(
    const float* __restrict__ x, float* __restrict__ part, int nper)
{
    __shared__ float sh[512];
    const int nsub = nper >> 4;
    const int grp = blockIdx.x >> 4, sub = blockIdx.x & 15;
    size_t base = (size_t)grp*nper + (size_t)sub*nsub;
    float s = 0.f, sq = 0.f;
    const float4* xv = reinterpret_cast<const float4*>(x + base);
    int n4 = nsub >> 2;
    for (int i = threadIdx.x; i < n4; i += 256){
        float4 v = xv[i];
        s  += v.x + v.y + v.z + v.w;
        sq += v.x*v.x + v.y*v.y + v.z*v.z + v.w*v.w;
    }
    sh[threadIdx.x] = s; sh[256 + threadIdx.x] = sq;
    __syncthreads();
    for (int off = 128; off > 0; off >>= 1){
        if (threadIdx.x < off){
            sh[threadIdx.x]       += sh[threadIdx.x + off];
            sh[256 + threadIdx.x] += sh[256 + threadIdx.x + off];
        }
        __syncthreads();
    }
    if (threadIdx.x == 0){
        part[blockIdx.x*2]     = sh[0];
        part[blockIdx.x*2 + 1] = sh[256];
    }
}
// stage 2: one tiny block finalizes all 32 groups
__global__ void __launch_bounds__(32) k_gnstats2(
    const float* __restrict__ part, float* __restrict__ st, int nper)
{
    int g = threadIdx.x;   // 0..31
    float s = 0.f, sq = 0.f;
    #pragma unroll
    for (int i = 0; i < 16; ++i){
        s  += part[(g*16 + i)*2];
        sq += part[(g*16 + i)*2 + 1];
    }
    float mean = s / (float)nper;
    float var  = sq / (float)nper - mean*mean;
    st[g*2]     = mean;
    st[g*2 + 1] = rsqrtf(var + 1e-5f);
}

// ================= gn1 apply + gelu, float4, in place =================
__global__ void __launch_bounds__(256) k_gnapply(
    float* __restrict__ x, const float* __restrict__ st,
    const float* __restrict__ gw, const float* __restrict__ gb)
{
    size_t i4 = (size_t)blockIdx.x*256 + threadIdx.x;
    size_t i  = i4 * 4;
    int c  = (int)((i >> 14) & 127);
    int bg = (int)(i >> 21) * 8 + (c >> 4);
    float m = st[bg*2], rs = st[bg*2 + 1];
    float w = gw[c], bb = gb[c];
    float4 v = reinterpret_cast<float4*>(x)[i4];
    v.x = gelu_f((v.x - m) * rs * w + bb);
    v.y = gelu_f((v.y - m) * rs * w + bb);
    v.z = gelu_f((v.z - m) * rs * w + bb);
    v.w = gelu_f((v.w - m) * rs * w + bb);
    reinterpret_cast<float4*>(x)[i4] = v;
}

// ================= gn2-apply + gelu + rh3 + geometry + refs =================
__global__ void __launch_bounds__(256) k_head(
    const float* __restrict__ t2, const float* __restrict__ st2,
    const float* __restrict__ g2w, const float* __restrict__ g2b,
    const float* __restrict__ rh3w, const float* __restrict__ rh3b,
    const float* __restrict__ l2e,
    float* __restrict__ out_mu, float* __restrict__ out_sigma,
    float* __restrict__ refp, float* __restrict__ sigf)
{
    int idx = blockIdx.x*256 + threadIdx.x;   // 0..65535
    int b = idx >> 14, pix = idx & 16383;
    float o0 = 0.f, o1 = 0.f;
    #pragma unroll 4
    for (int c = 0; c < 64; ++c){
        int bg = b*8 + (c >> 3);
        float m  = st2[bg*2], rs = st2[bg*2 + 1];
        float v  = t2[((size_t)(b*64 + c))*16384 + pix];
        float hg = gelu_f((v - m) * rs * g2w[c] + g2b[c]);
        o0 = fmaf(rh3w[c],      hg, o0);
        o1 = fmaf(rh3w[64 + c], hg, o1);
    }
    float mu01 = sigm_f(o0 + rh3b[0]);
    float mu   = mu01 * 55.0f;
    float sg   = fmaxf(o1 + rh3b[1], 0.001f) * 55.0f;

    float ux, uy, uz;
    geom_f(pix >> 9, pix & 511, ux, uy, uz);
    float pxe = mu*ux*l2e[0] + mu*uy*l2e[4] + mu*uz*l2e[8]  + l2e[12];
    float pye = mu*ux*l2e[1] + mu*uy*l2e[5] + mu*uz*l2e[9]  + l2e[13];
    float rx = sigm_f(4.0f * ((pxe + 55.0f) * (1.0f/110.0f) - 0.5f));
    float ry = sigm_f(4.0f * ((pye + 55.0f) * (1.0f/110.0f) - 0.5f));

    refp[idx*2]     = rx;
    refp[idx*2 + 1] = ry;
    sigf[idx*2]     = sg;
    sigf[idx*2 + 1] = 1.0f / (sg + 1e-6f);
    out_mu[idx]     = mu01;
    out_sigma[idx]  = sg;
}

// ================= deformable attention sampler =================
__global__ void __launch_bounds__(256) k_msda(
    const float* __restrict__ v,      // [b][65536][128]
    const float* __restrict__ offaw,  // [b][16384][144]
    const float* __restrict__ ref,    // [b][16384][2]
    float* __restrict__ out)          // [b][16384][128]
{
    int gq = blockIdx.x*2 + (threadIdx.x >> 7);
    int t  = threadIdx.x & 127;
    int head = t >> 4, c = t & 15;
    int b = gq >> 14;
    const float* oa = offaw + (size_t)gq*144;
    float rx = ref[gq*2], ry = ref[gq*2 + 1];

    float lg[6];
    float mx = -1e30f;
    #pragma unroll
    for (int p = 0; p < 6; ++p){ lg[p] = oa[96 + head*6 + p]; mx = fmaxf(mx, lg[p]); }
    float den = 0.f;
    #pragma unroll
    for (int p = 0; p < 6; ++p){ lg[p] = expf(lg[p] - mx); den += lg[p]; }
    float iden = 1.f / den;

    const float* vb = v + (size_t)b*65536*128 + head*16 + c;
    float acc = 0.f;
    #pragma unroll
    for (int p = 0; p < 6; ++p){
        float ox = oa[(head*6 + p)*2 + 0];
        float oy = oa[(head*6 + p)*2 + 1];
        float xs = (rx + ox * (1.0f/256.0f)) * 256.0f - 0.5f;
        float ys = (ry + oy * (1.0f/256.0f)) * 256.0f - 0.5f;
        float x0f = floorf(xs), y0f = floorf(ys);
        float wx = xs - x0f, wy = ys - y0f;
        int x0 = (int)x0f, y0 = (int)y0f;
        float s = 0.f;
        #pragma unroll
        for (int dy = 0; dy < 2; ++dy){
            int yi = y0 + dy;
            bool vy = (yi >= 0) && (yi < 256);
            int yc = min(max(yi, 0), 255);
            float wyv = dy ? wy : (1.f - wy);
            #pragma unroll
            for (int dx = 0; dx < 2; ++dx){
                int xi = x0 + dx;
                bool vx = (xi >= 0) && (xi < 256);
                int xc = min(max(xi, 0), 255);
                float wv = wyv * (dx ? wx : (1.f - wx));
                if (vx && vy)
                    s = fmaf(vb[(size_t)(yc*256 + xc)*128], wv, s);
            }
        }
        acc = fmaf(lg[p]*iden, s, acc);
    }
    out[(size_t)gq*128 + t] = acc;
}

// ================= host launcher =================
extern "C" void kernel_launch(void* const* d_in, const int* in_sizes, int n_in,
                              void* d_out, int out_size)
{
    const float* x_rv  = (const float*)d_in[0];
    const float* bev   = (const float*)d_in[1];
    const float* l2e   = (const float*)d_in[2];
    const float* pq_w  = (const float*)d_in[3];
    const float* pq_b  = (const float*)d_in[4];
    const float* pv_w  = (const float*)d_in[5];
    const float* pv_b  = (const float*)d_in[6];
    const float* po_w  = (const float*)d_in[7];
    const float* po_b  = (const float*)d_in[8];
    const float* qs1_w = (const float*)d_in[9];
    const float* qs1_b = (const float*)d_in[10];
    const float* qs2_w = (const float*)d_in[11];
    const float* qs2_b = (const float*)d_in[12];
    const float* rh1_w = (const float*)d_in[13];
    const float* rh1_b = (const float*)d_in[14];
    const float* gn1_w = (const float*)d_in[15];
    const float* gn1_b = (const float*)d_in[16];
    const float* rh2_w = (const float*)d_in[17];
    const float* gn2_w = (const float*)d_in[18];
    const float* gn2_b = (const float*)d_in[19];
    const float* rh3_w = (const float*)d_in[20];
    const float* rh3_b = (const float*)d_in[21];
    const float* so_w  = (const float*)d_in[22];
    const float* so_b  = (const float*)d_in[23];
    const float* aw_w  = (const float*)d_in[24];
    const float* aw_b  = (const float*)d_in[25];
    const float* vp_w  = (const float*)d_in[26];
    const float* vp_b  = (const float*)d_in[27];
    const float* op_w  = (const float*)d_in[28];
    const float* op_b  = (const float*)d_in[29];

    float *wcombT, *bcomb, *woaT, *boa, *wyT, *by, *pqT, *rh1T, *qs1T, *bqs1,
          *rh2T, *vmap, *t1, *t2, *stats, *part, *refp, *sigf, *qt, *offaw, *attn;
    cudaGetSymbolAddress((void**)&wcombT, g_wcombT);
    cudaGetSymbolAddress((void**)&bcomb,  g_bcomb);
    cudaGetSymbolAddress((void**)&woaT,   g_woaT);
    cudaGetSymbolAddress((void**)&boa,    g_boa);
    cudaGetSymbolAddress((void**)&wyT,    g_wyT);
    cudaGetSymbolAddress((void**)&by,     g_by);
    cudaGetSymbolAddress((void**)&pqT,    g_pqT);
    cudaGetSymbolAddress((void**)&rh1T,   g_rh1T);
    cudaGetSymbolAddress((void**)&qs1T,   g_qs1T);
    cudaGetSymbolAddress((void**)&bqs1,   g_bqs1);
    cudaGetSymbolAddress((void**)&rh2T,   g_rh2T);
    cudaGetSymbolAddress((void**)&vmap,   g_v);
    cudaGetSymbolAddress((void**)&t1,     g_t1);
    cudaGetSymbolAddress((void**)&t2,     g_t2);
    cudaGetSymbolAddress((void**)&stats,  g_stats);
    cudaGetSymbolAddress((void**)&part,   g_part);
    cudaGetSymbolAddress((void**)&refp,   g_ref);
    cudaGetSymbolAddress((void**)&sigf,   g_sig);
    cudaGetSymbolAddress((void**)&qt,     g_qt);
    cudaGetSymbolAddress((void**)&offaw,  g_offaw);
    cudaGetSymbolAddress((void**)&attn,   g_attn);

    float* y_out     = (float*)d_out;                   // [4][128][16384] channel-major
    float* mu_out    = y_out + (size_t)4*128*16384;     // [4][16384]
    float* sigma_out = mu_out + 65536;                  // [4][16384]

    // 1. weight folding + transposes (incl. pq folded into qs1)
    k_prep<<<763, 256>>>(vp_w, pv_w, pv_b, vp_b, so_w, so_b, aw_w, aw_b,
                         qs2_w, qs2_b, po_w, po_b, op_w, op_b,
                         pq_w, pq_b, rh1_w, qs1_w, qs1_b, rh2_w,
                         wcombT, bcomb, woaT, boa, wyT, by,
                         pqT, rh1T, qs1T, bqs1, rh2T);
    // 2. value map (vp o pv)(bev), pixel-major
    k_gemm5<128,128,1,0,0><<<dim3(1024,4), 256>>>(bev, wcombT, bcomb, vmap, nullptr, 65536);
    // 3. rh1(concat(x, uvec)), channel-major
    k_gemm5<131,128,2,1,0><<<dim3(256,4), 256>>>(x_rv, rh1T, rh1_b, t1, nullptr, 16384);
    // 4-5. gn1 (two-stage) + gelu
    k_gnstats1<<<512, 256>>>(t1, part, 16*16384);
    k_gnstats2<<<1, 32>>>(part, stats, 16*16384);
    k_gnapply<<<8192, 256>>>(t1, stats, gn1_w, gn1_b);
    // 6. 3x3 wrap conv 128->64
    k_conv3<<<dim3(2,32,4), 256>>>(t1, rh2T, t2);
    // 7. gn2 stats (two-stage)
    k_gnstats1<<<512, 256>>>(t2, part, 8*16384);
    k_gnstats2<<<1, 32>>>(part, stats + 64, 8*16384);
    // 8. head: gn2+gelu+rh3+geometry+refs+outputs
    k_head<<<256, 256>>>(t2, stats + 64, gn2_w, gn2_b, rh3_w, rh3_b, l2e,
                         mu_out, sigma_out, refp, sigf);
    // 9. qt = gelu((qs1 o pq)(x) + sig-term), pixel-major (Q0 GEMM eliminated)
    k_gemm5<130,128,3,0,1><<<dim3(256,4), 256>>>(x_rv, qs1T, bqs1, qt, sigf, 16384);
    // 10. offsets+logits straight from qt via folded (so/aw)@qs2
    k_gemm5<128,144,0,0,0><<<dim3(256,4), 288>>>(qt, woaT, boa, offaw, nullptr, 16384);
    // 11. deformable attention gather
    k_msda<<<32768, 256>>>(vmap, offaw, refp, attn);
    // 12. y = (po@qs2) qt + (po@op) attn + b, channel-major straight into d_out
    k_gemm5<256,128,4,1,0><<<dim3(256,4), 256>>>(qt, wyT, by, y_out, attn, 16384);
}